// round 3
// baseline (speedup 1.0000x reference)
#include <cuda_runtime.h>
#include <cstdint>

#define BATCH 8
#define NSEQ 1024
#define DIM 768
#define NH 16
#define HD 48
#define SCALE 0.14433756729740643f  /* 48^-0.5 */

// ---------------- scratch (static __device__, allocation-guard safe) ----------
__device__ __align__(256) float g_q[BATCH * NH * NSEQ * HD];
__device__ __align__(256) float g_k[BATCH * NH * NSEQ * HD];
__device__ __align__(256) float g_v[BATCH * NH * NSEQ * HD];
__device__ __align__(256) float g_S[(size_t)BATCH * NH * NSEQ * NSEQ];
__device__ __align__(256) float g_O[BATCH * NSEQ * DIM];

// ---------------- helpers -----------------------------------------------------
__device__ __forceinline__ uint32_t f2tf(float x) {
    uint32_t r;
    asm("cvt.rna.tf32.f32 %0, %1;" : "=r"(r) : "f"(x));
    return r;
}
__device__ __forceinline__ void mma8(float* c, const uint32_t* a, const uint32_t* b) {
    asm volatile(
        "mma.sync.aligned.m16n8k8.row.col.f32.tf32.tf32.f32 "
        "{%0,%1,%2,%3},{%4,%5,%6,%7},{%8,%9},{%0,%1,%2,%3};"
        : "+f"(c[0]), "+f"(c[1]), "+f"(c[2]), "+f"(c[3])
        : "r"(a[0]), "r"(a[1]), "r"(a[2]), "r"(a[3]), "r"(b[0]), "r"(b[1]));
}
// packed fp32x2 FMA (two exact IEEE fp32 FMAs per instruction)
__device__ __forceinline__ unsigned long long fma2(
    unsigned long long a, unsigned long long b, unsigned long long c) {
    unsigned long long d;
    asm("fma.rn.f32x2 %0, %1, %2, %3;" : "=l"(d) : "l"(a), "l"(b), "l"(c));
    return d;
}
__device__ __forceinline__ unsigned long long pack2(float x, float y) {
    unsigned long long r;
    asm("mov.b64 %0, {%1, %2};" : "=l"(r) : "f"(x), "f"(y));
    return r;
}

// ---------------- generic tf32 GEMM: C = A @ W^T (+bias), double-buffered -----
// Block 128x128, K-tile 16, 8 warps (2Mx4N), warp tile 64x32. K % 16 == 0.
// MODE 0: qkv scatter. MODE 1: plain C+bias. MODE 2: batched store to g_S.
template <int MODE>
__global__ __launch_bounds__(256, 2) void mm_tf32(
    const float* __restrict__ A, const float* __restrict__ W,
    const float* __restrict__ bias, float* __restrict__ C,
    int K, int Nc, size_t sA, size_t sW) {
    __shared__ uint32_t As[2][128][20];
    __shared__ uint32_t Ws[2][128][20];

    const int tid = threadIdx.x;
    const int m0 = blockIdx.y * 128;
    const int n0 = blockIdx.x * 128;
    const int bz = blockIdx.z;

    const float* Ag = A + (size_t)bz * sA;
    const float* Wg = W + (size_t)bz * sW;

    const int warp = tid >> 5, lane = tid & 31;
    const int wm = warp >> 2, wn = warp & 3;
    const int g = lane >> 2, t = lane & 3;

    const int r0 = tid >> 2;            // 0..63 (also loads r0+64)
    const int c0 = (tid & 3) * 4;       // 0,4,8,12

    float4 pa[2], pw[2];

    float acc[4][4][4];
#pragma unroll
    for (int i = 0; i < 4; i++)
#pragma unroll
        for (int j = 0; j < 4; j++)
#pragma unroll
            for (int e = 0; e < 4; e++) acc[i][j][e] = 0.f;

#define MM_LD(kt)                                                              \
    do {                                                                       \
        pa[0] = *(const float4*)(Ag + (size_t)(m0 + r0) * K + (kt) + c0);      \
        pa[1] = *(const float4*)(Ag + (size_t)(m0 + r0 + 64) * K + (kt) + c0); \
        pw[0] = *(const float4*)(Wg + (size_t)(n0 + r0) * K + (kt) + c0);      \
        pw[1] = *(const float4*)(Wg + (size_t)(n0 + r0 + 64) * K + (kt) + c0); \
    } while (0)
#define MM_ST(buf)                                                             \
    do {                                                                       \
        As[buf][r0][c0 + 0] = f2tf(pa[0].x); As[buf][r0][c0 + 1] = f2tf(pa[0].y); \
        As[buf][r0][c0 + 2] = f2tf(pa[0].z); As[buf][r0][c0 + 3] = f2tf(pa[0].w); \
        As[buf][r0 + 64][c0 + 0] = f2tf(pa[1].x); As[buf][r0 + 64][c0 + 1] = f2tf(pa[1].y); \
        As[buf][r0 + 64][c0 + 2] = f2tf(pa[1].z); As[buf][r0 + 64][c0 + 3] = f2tf(pa[1].w); \
        Ws[buf][r0][c0 + 0] = f2tf(pw[0].x); Ws[buf][r0][c0 + 1] = f2tf(pw[0].y); \
        Ws[buf][r0][c0 + 2] = f2tf(pw[0].z); Ws[buf][r0][c0 + 3] = f2tf(pw[0].w); \
        Ws[buf][r0 + 64][c0 + 0] = f2tf(pw[1].x); Ws[buf][r0 + 64][c0 + 1] = f2tf(pw[1].y); \
        Ws[buf][r0 + 64][c0 + 2] = f2tf(pw[1].z); Ws[buf][r0 + 64][c0 + 3] = f2tf(pw[1].w); \
    } while (0)

    MM_LD(0);
    MM_ST(0);
    __syncthreads();

    int buf = 0;
    for (int kt = 16;; kt += 16) {
        const bool more = kt < K;
        if (more) MM_LD(kt);
#pragma unroll
        for (int ks = 0; ks < 16; ks += 8) {
            uint32_t af[4][4], bf[4][2];
#pragma unroll
            for (int mt = 0; mt < 4; mt++) {
                const int r = wm * 64 + mt * 16 + g;
                af[mt][0] = As[buf][r][ks + t];
                af[mt][1] = As[buf][r + 8][ks + t];
                af[mt][2] = As[buf][r][ks + t + 4];
                af[mt][3] = As[buf][r + 8][ks + t + 4];
            }
#pragma unroll
            for (int nt = 0; nt < 4; nt++) {
                const int n = wn * 32 + nt * 8 + g;
                bf[nt][0] = Ws[buf][n][ks + t];
                bf[nt][1] = Ws[buf][n][ks + t + 4];
            }
#pragma unroll
            for (int mt = 0; mt < 4; mt++)
#pragma unroll
                for (int nt = 0; nt < 4; nt++) mma8(acc[mt][nt], af[mt], bf[nt]);
        }
        if (!more) break;
        MM_ST(buf ^ 1);
        __syncthreads();
        buf ^= 1;
    }

#pragma unroll
    for (int mt = 0; mt < 4; mt++) {
#pragma unroll
        for (int nt = 0; nt < 4; nt++) {
#pragma unroll
            for (int half = 0; half < 2; half++) {
                const int m = m0 + wm * 64 + mt * 16 + g + half * 8;
                const int c = n0 + wn * 32 + nt * 8 + 2 * t;
                const float v0 = acc[mt][nt][half * 2 + 0];
                const float v1 = acc[mt][nt][half * 2 + 1];
                if (MODE == 0) {
#pragma unroll
                    for (int e = 0; e < 2; e++) {
                        const int cc = c + e;
                        float v = (e ? v1 : v0) + bias[cc];
                        const int b = m >> 10, n = m & 1023;
                        const int tt = cc / DIM;
                        const int rr = cc - tt * DIM;
                        const int h = rr / HD, d = rr - h * HD;
                        const int idx = (((b * NH + h) * NSEQ) + n) * HD + d;
                        if (tt == 0)      g_q[idx] = v * SCALE;
                        else if (tt == 1) g_k[idx] = v;
                        else              g_v[idx] = v;
                    }
                } else if (MODE == 1) {
                    float2 o = make_float2(v0 + bias[c], v1 + bias[c + 1]);
                    *(float2*)(C + (size_t)m * Nc + c) = o;
                } else {
                    float* Cb = g_S + (size_t)bz * NSEQ * NSEQ;
                    *(float2*)(Cb + (size_t)m * NSEQ + c) = make_float2(v0, v1);
                }
            }
        }
    }
#undef MM_LD
#undef MM_ST
}

// ---------------- K3: fused mix1 -> softmax -> mix2, in place on g_S ---------
__global__ __launch_bounds__(256) void mix_softmax_kernel(
    const float* __restrict__ wl, const float* __restrict__ bl,
    const float* __restrict__ ww, const float* __restrict__ bw) {
    extern __shared__ float s[];  // [16][1024]
    __shared__ unsigned long long wls2[256], wws2[256], bls2[16], bws2[16];

    const int tid = threadIdx.x;
    const int bq = blockIdx.x;
    const int b = bq >> 10, q = bq & 1023;

    wls2[tid] = pack2(wl[tid], wl[tid]);
    wws2[tid] = pack2(ww[tid], ww[tid]);
    if (tid < 16) {
        bls2[tid] = pack2(bl[tid], bl[tid]);
        bws2[tid] = pack2(bw[tid], bw[tid]);
    }

    const size_t rowbase = (size_t)(b * NH) * NSEQ * NSEQ + (size_t)q * NSEQ;
#pragma unroll
    for (int h = 0; h < NH; h++) {
        const float4* src = (const float4*)(g_S + rowbase + (size_t)h * NSEQ * NSEQ);
        ((float4*)s)[h * 256 + tid] = src[tid];
    }
    __syncthreads();

    // mix1 (packed f32x2, 2 columns/iter), in place
    unsigned long long* sp = (unsigned long long*)s;
#pragma unroll
    for (int it = 0; it < 2; it++) {
        const int p = tid + it * 256;  // column-pair index 0..511
        unsigned long long sv[NH], mv[NH];
#pragma unroll
        for (int h = 0; h < NH; h++) sv[h] = sp[h * 512 + p];
#pragma unroll
        for (int gg = 0; gg < NH; gg++) {
            unsigned long long acc = bls2[gg];
#pragma unroll
            for (int h = 0; h < NH; h++) acc = fma2(wls2[gg * NH + h], sv[h], acc);
            mv[gg] = acc;
        }
#pragma unroll
        for (int gg = 0; gg < NH; gg++) sp[gg * 512 + p] = mv[gg];
    }
    __syncthreads();

    // softmax per head row
    const int lane = tid & 31, warp = tid >> 5;
    for (int gg = warp; gg < NH; gg += 8) {
        float* row = s + gg * NSEQ;
        float mx = -1e30f;
        for (int k = lane; k < NSEQ; k += 32) mx = fmaxf(mx, row[k]);
#pragma unroll
        for (int off = 16; off > 0; off >>= 1) mx = fmaxf(mx, __shfl_xor_sync(0xffffffffu, mx, off));
        float sum = 0.f;
        for (int k = lane; k < NSEQ; k += 32) {
            float e = __expf(row[k] - mx);
            row[k] = e;
            sum += e;
        }
#pragma unroll
        for (int off = 16; off > 0; off >>= 1) sum += __shfl_xor_sync(0xffffffffu, sum, off);
        const float inv = 1.f / sum;
        for (int k = lane; k < NSEQ; k += 32) row[k] *= inv;
    }
    __syncthreads();

    // mix2 (packed), write to g_S
#pragma unroll
    for (int it = 0; it < 2; it++) {
        const int p = tid + it * 256;
        unsigned long long pv[NH];
#pragma unroll
        for (int h = 0; h < NH; h++) pv[h] = sp[h * 512 + p];
#pragma unroll
        for (int gg = 0; gg < NH; gg++) {
            unsigned long long acc = bws2[gg];
#pragma unroll
            for (int h = 0; h < NH; h++) acc = fma2(wws2[gg * NH + h], pv[h], acc);
            *(unsigned long long*)(g_S + rowbase + (size_t)gg * NSEQ * NSEQ + 2 * p) = acc;
        }
    }
}

// ---------------- K4: O = P @ V per (b,h), tf32 mma, double-buffered ----------
__global__ __launch_bounds__(256) void pv_tf32() {
    __shared__ uint32_t Ps[2][128][36];
    __shared__ uint32_t Vs[2][HD][36];

    const int bh = blockIdx.z;
    const int tid = threadIdx.x;
    const int qbase = blockIdx.x * 128;
    const float* Pg = g_S + (size_t)bh * NSEQ * NSEQ + (size_t)qbase * NSEQ;
    const float* Vg = g_v + (size_t)bh * NSEQ * HD;

    const int warp = tid >> 5, lane = tid & 31;
    const int wm = warp >> 1, wn = warp & 1;
    const int g = lane >> 2, t = lane & 3;

    const int pr = tid >> 3;          // 0..31 (rows pr, pr+32, pr+64, pr+96)
    const int pc = (tid & 7) * 4;     // 0..28
    const int vk = tid & 31;          // V k index
    const int vd0 = tid >> 5;         // V d base (d = vd0 + 8j)

    float4 pp[4];
    float pvr[6];

    float acc[2][3][4];
#pragma unroll
    for (int i = 0; i < 2; i++)
#pragma unroll
        for (int j = 0; j < 3; j++)
#pragma unroll
            for (int e = 0; e < 4; e++) acc[i][j][e] = 0.f;

#define PV_LD(kt)                                                               \
    do {                                                                        \
        _Pragma("unroll")                                                       \
        for (int j = 0; j < 4; j++)                                             \
            pp[j] = *(const float4*)(Pg + (size_t)(pr + 32 * j) * NSEQ + (kt) + pc); \
        _Pragma("unroll")                                                       \
        for (int j = 0; j < 6; j++)                                             \
            pvr[j] = Vg[(size_t)((kt) + vk) * HD + vd0 + 8 * j];                \
    } while (0)
#define PV_ST(buf)                                                              \
    do {                                                                        \
        _Pragma("unroll")                                                       \
        for (int j = 0; j < 4; j++) {                                           \
            Ps[buf][pr + 32 * j][pc + 0] = f2tf(pp[j].x);                       \
            Ps[buf][pr + 32 * j][pc + 1] = f2tf(pp[j].y);                       \
            Ps[buf][pr + 32 * j][pc + 2] = f2tf(pp[j].z);                       \
            Ps[buf][pr + 32 * j][pc + 3] = f2tf(pp[j].w);                       \
        }                                                                       \
        _Pragma("unroll")                                                       \
        for (int j = 0; j < 6; j++) Vs[buf][vd0 + 8 * j][vk] = f2tf(pvr[j]);    \
    } while (0)

    PV_LD(0);
    PV_ST(0);
    __syncthreads();

    int buf = 0;
    for (int kt = 32;; kt += 32) {
        const bool more = kt < NSEQ;
        if (more) PV_LD(kt);
#pragma unroll
        for (int ks = 0; ks < 32; ks += 8) {
            uint32_t af[2][4], bf[3][2];
#pragma unroll
            for (int mt = 0; mt < 2; mt++) {
                const int r = wm * 32 + mt * 16 + g;
                af[mt][0] = Ps[buf][r][ks + t];
                af[mt][1] = Ps[buf][r + 8][ks + t];
                af[mt][2] = Ps[buf][r][ks + t + 4];
                af[mt][3] = Ps[buf][r + 8][ks + t + 4];
            }
#pragma unroll
            for (int nt = 0; nt < 3; nt++) {
                const int n = wn * 24 + nt * 8 + g;
                bf[nt][0] = Vs[buf][n][ks + t];
                bf[nt][1] = Vs[buf][n][ks + t + 4];
            }
#pragma unroll
            for (int mt = 0; mt < 2; mt++)
#pragma unroll
                for (int nt = 0; nt < 3; nt++) mma8(acc[mt][nt], af[mt], bf[nt]);
        }
        if (!more) break;
        PV_ST(buf ^ 1);
        __syncthreads();
        buf ^= 1;
    }

    const int b = bh >> 4, h = bh & 15;
#pragma unroll
    for (int mt = 0; mt < 2; mt++)
#pragma unroll
        for (int nt = 0; nt < 3; nt++)
#pragma unroll
            for (int half = 0; half < 2; half++) {
                const int q = qbase + wm * 32 + mt * 16 + g + half * 8;
                const int d = wn * 24 + nt * 8 + 2 * t;
                float2 o = make_float2(acc[mt][nt][half * 2], acc[mt][nt][half * 2 + 1]);
                *(float2*)(g_O + (size_t)(b * NSEQ + q) * DIM + h * HD + d) = o;
            }
#undef PV_LD
#undef PV_ST
}

// ---------------- launch ------------------------------------------------------
extern "C" void kernel_launch(void* const* d_in, const int* in_sizes, int n_in,
                              void* d_out, int out_size) {
    const float* x      = (const float*)d_in[0];
    const float* w_qkv  = (const float*)d_in[1];
    const float* b_qkv  = (const float*)d_in[2];
    const float* w_l    = (const float*)d_in[3];
    const float* b_l    = (const float*)d_in[4];
    const float* w_w    = (const float*)d_in[5];
    const float* b_w    = (const float*)d_in[6];
    const float* w_proj = (const float*)d_in[7];
    const float* b_proj = (const float*)d_in[8];
    float* out = (float*)d_out;

    cudaFuncSetAttribute(mix_softmax_kernel,
                         cudaFuncAttributeMaxDynamicSharedMemorySize, 16 * NSEQ * 4);

    float* gq_p; cudaGetSymbolAddress((void**)&gq_p, g_q);
    float* gk_p; cudaGetSymbolAddress((void**)&gk_p, g_k);
    float* gO_p; cudaGetSymbolAddress((void**)&gO_p, g_O);

    // K1: QKV projection  [M=8192, N=2304, K=768]
    mm_tf32<0><<<dim3(3 * DIM / 128, BATCH * NSEQ / 128, 1), 256>>>(
        x, w_qkv, b_qkv, nullptr, DIM, 3 * DIM, 0, 0);
    // K2: logits S = q @ k^T per (b,h)  [z=128, M=N=1024, K=48]
    mm_tf32<2><<<dim3(NSEQ / 128, NSEQ / 128, BATCH * NH), 256>>>(
        gq_p, gk_p, nullptr, nullptr, HD, NSEQ,
        (size_t)NSEQ * HD, (size_t)NSEQ * HD);
    // K3: mix1 + softmax + mix2 (in place)
    mix_softmax_kernel<<<BATCH * NSEQ, 256, 16 * NSEQ * 4>>>(w_l, b_l, w_w, b_w);
    // K4: P @ V -> g_O
    pv_tf32<<<dim3(NSEQ / 128, 1, BATCH * NH), 256>>>();
    // K5: output projection  [M=8192, N=768, K=768]
    mm_tf32<1><<<dim3(DIM / 128, BATCH * NSEQ / 128, 1), 256>>>(
        gO_p, w_proj, b_proj, out, DIM, DIM, 0, 0);
}

// round 4
// speedup vs baseline: 1.0002x; 1.0002x over previous
#include <cuda_runtime.h>
#include <cstdint>

#define BATCH 8
#define NSEQ 1024
#define DIM 768
#define NH 16
#define HD 48
#define SCALE 0.14433756729740643f  /* 48^-0.5 */

// ---------------- scratch (static __device__, allocation-guard safe) ----------
__device__ __align__(256) float g_q[BATCH * NH * NSEQ * HD];
__device__ __align__(256) float g_k[BATCH * NH * NSEQ * HD];
__device__ __align__(256) float g_v[BATCH * NH * NSEQ * HD];
__device__ __align__(256) float g_S[(size_t)BATCH * NH * NSEQ * NSEQ];
__device__ __align__(256) float g_O[BATCH * NSEQ * DIM];

// ---------------- helpers -----------------------------------------------------
__device__ __forceinline__ uint32_t f2tf(float x) {
    uint32_t r;
    asm("cvt.rna.tf32.f32 %0, %1;" : "=r"(r) : "f"(x));
    return r;
}
__device__ __forceinline__ void mma8(float* c, const uint32_t* a, const uint32_t* b) {
    asm volatile(
        "mma.sync.aligned.m16n8k8.row.col.f32.tf32.tf32.f32 "
        "{%0,%1,%2,%3},{%4,%5,%6,%7},{%8,%9},{%0,%1,%2,%3};"
        : "+f"(c[0]), "+f"(c[1]), "+f"(c[2]), "+f"(c[3])
        : "r"(a[0]), "r"(a[1]), "r"(a[2]), "r"(a[3]), "r"(b[0]), "r"(b[1]));
}
__device__ __forceinline__ unsigned long long fma2(
    unsigned long long a, unsigned long long b, unsigned long long c) {
    unsigned long long d;
    asm("fma.rn.f32x2 %0, %1, %2, %3;" : "=l"(d) : "l"(a), "l"(b), "l"(c));
    return d;
}
__device__ __forceinline__ unsigned long long pack2(float x, float y) {
    unsigned long long r;
    asm("mov.b64 %0, {%1, %2};" : "=l"(r) : "f"(x), "f"(y));
    return r;
}

#define CP16(dst_u32, src_ptr) \
    asm volatile("cp.async.cg.shared.global [%0], [%1], 16;" :: "r"(dst_u32), "l"(src_ptr))
#define CP_COMMIT() asm volatile("cp.async.commit_group;" ::)
#define CP_WAIT0()  asm volatile("cp.async.wait_group 0;" ::)

// ---------------- generic tf32 GEMM via cp.async double buffer ----------------
// Block 128x128, K-tile 16, 8 warps (2Mx4N), warp tile 64x32. K % 16 == 0.
// smem holds RAW fp32; cvt to tf32 at fragment load.
// MODE 0: qkv scatter. MODE 1: plain C+bias. MODE 2: batched store to g_S.
template <int MODE>
__global__ __launch_bounds__(256) void mm_tf32(
    const float* __restrict__ A, const float* __restrict__ W,
    const float* __restrict__ bias, float* __restrict__ C,
    int K, int Nc, size_t sA, size_t sW) {
    __shared__ float As[2][128][20];   // stride 20 -> conflict-free fragment loads
    __shared__ float Ws[2][128][20];

    const int tid = threadIdx.x;
    const int m0 = blockIdx.y * 128;
    const int n0 = blockIdx.x * 128;
    const int bz = blockIdx.z;

    const float* Ag = A + (size_t)bz * sA;
    const float* Wg = W + (size_t)bz * sW;

    const int warp = tid >> 5, lane = tid & 31;
    const int wm = warp >> 2, wn = warp & 3;
    const int g = lane >> 2, t = lane & 3;

    const int lr = tid >> 2;          // 0..63 (also row lr+64)
    const int lc = (tid & 3) * 4;     // 0,4,8,12

    const uint32_t sa = (uint32_t)__cvta_generic_to_shared(&As[0][0][0]);
    const uint32_t sw = (uint32_t)__cvta_generic_to_shared(&Ws[0][0][0]);
    const uint32_t d0 = (lr * 20 + lc) * 4;
    const uint32_t d1 = ((lr + 64) * 20 + lc) * 4;
    const uint32_t bufoff = 128 * 20 * 4;

#define MM_CP(buf, kt)                                                         \
    do {                                                                       \
        CP16(sa + (buf) * bufoff + d0, Ag + (size_t)(m0 + lr) * K + (kt) + lc);      \
        CP16(sa + (buf) * bufoff + d1, Ag + (size_t)(m0 + lr + 64) * K + (kt) + lc); \
        CP16(sw + (buf) * bufoff + d0, Wg + (size_t)(n0 + lr) * K + (kt) + lc);      \
        CP16(sw + (buf) * bufoff + d1, Wg + (size_t)(n0 + lr + 64) * K + (kt) + lc); \
        CP_COMMIT();                                                           \
    } while (0)

    float acc[4][4][4];
#pragma unroll
    for (int i = 0; i < 4; i++)
#pragma unroll
        for (int j = 0; j < 4; j++)
#pragma unroll
            for (int e = 0; e < 4; e++) acc[i][j][e] = 0.f;

    MM_CP(0, 0);
    CP_WAIT0();
    __syncthreads();

    int buf = 0;
    for (int kt = 16;; kt += 16) {
        const bool more = kt < K;
        if (more) MM_CP(buf ^ 1, kt);   // fills other buffer while we compute
#pragma unroll
        for (int ks = 0; ks < 16; ks += 8) {
            uint32_t af[4][4], bf[4][2];
#pragma unroll
            for (int mt = 0; mt < 4; mt++) {
                const int r = wm * 64 + mt * 16 + g;
                af[mt][0] = f2tf(As[buf][r][ks + t]);
                af[mt][1] = f2tf(As[buf][r + 8][ks + t]);
                af[mt][2] = f2tf(As[buf][r][ks + t + 4]);
                af[mt][3] = f2tf(As[buf][r + 8][ks + t + 4]);
            }
#pragma unroll
            for (int nt = 0; nt < 4; nt++) {
                const int n = wn * 32 + nt * 8 + g;
                bf[nt][0] = f2tf(Ws[buf][n][ks + t]);
                bf[nt][1] = f2tf(Ws[buf][n][ks + t + 4]);
            }
#pragma unroll
            for (int mt = 0; mt < 4; mt++)
#pragma unroll
                for (int nt = 0; nt < 4; nt++) mma8(acc[mt][nt], af[mt], bf[nt]);
        }
        if (!more) break;
        CP_WAIT0();
        __syncthreads();   // separates compute-on-buf from next cp into buf
        buf ^= 1;
    }

#pragma unroll
    for (int mt = 0; mt < 4; mt++) {
#pragma unroll
        for (int nt = 0; nt < 4; nt++) {
#pragma unroll
            for (int half = 0; half < 2; half++) {
                const int m = m0 + wm * 64 + mt * 16 + g + half * 8;
                const int c = n0 + wn * 32 + nt * 8 + 2 * t;
                const float v0 = acc[mt][nt][half * 2 + 0];
                const float v1 = acc[mt][nt][half * 2 + 1];
                if (MODE == 0) {
#pragma unroll
                    for (int e = 0; e < 2; e++) {
                        const int cc = c + e;
                        float v = (e ? v1 : v0) + bias[cc];
                        const int b = m >> 10, n = m & 1023;
                        const int tt = cc / DIM;
                        const int rr = cc - tt * DIM;
                        const int h = rr / HD, d = rr - h * HD;
                        const int idx = (((b * NH + h) * NSEQ) + n) * HD + d;
                        if (tt == 0)      g_q[idx] = v * SCALE;
                        else if (tt == 1) g_k[idx] = v;
                        else              g_v[idx] = v;
                    }
                } else if (MODE == 1) {
                    float2 o = make_float2(v0 + bias[c], v1 + bias[c + 1]);
                    *(float2*)(C + (size_t)m * Nc + c) = o;
                } else {
                    float* Cb = g_S + (size_t)bz * NSEQ * NSEQ;
                    *(float2*)(Cb + (size_t)m * NSEQ + c) = make_float2(v0, v1);
                }
            }
        }
    }
#undef MM_CP
}

// ---------------- K3: fused mix1 -> softmax -> mix2, in place on g_S ---------
__global__ __launch_bounds__(256) void mix_softmax_kernel(
    const float* __restrict__ wl, const float* __restrict__ bl,
    const float* __restrict__ ww, const float* __restrict__ bw) {
    extern __shared__ float s[];  // [16][1024]
    __shared__ unsigned long long wls2[256], wws2[256], bls2[16], bws2[16];

    const int tid = threadIdx.x;
    const int bq = blockIdx.x;
    const int b = bq >> 10, q = bq & 1023;

    wls2[tid] = pack2(wl[tid], wl[tid]);
    wws2[tid] = pack2(ww[tid], ww[tid]);
    if (tid < 16) {
        bls2[tid] = pack2(bl[tid], bl[tid]);
        bws2[tid] = pack2(bw[tid], bw[tid]);
    }

    const size_t rowbase = (size_t)(b * NH) * NSEQ * NSEQ + (size_t)q * NSEQ;
#pragma unroll
    for (int h = 0; h < NH; h++) {
        const float4* src = (const float4*)(g_S + rowbase + (size_t)h * NSEQ * NSEQ);
        ((float4*)s)[h * 256 + tid] = src[tid];
    }
    __syncthreads();

    unsigned long long* sp = (unsigned long long*)s;
#pragma unroll
    for (int it = 0; it < 2; it++) {
        const int p = tid + it * 256;
        unsigned long long sv[NH], mv[NH];
#pragma unroll
        for (int h = 0; h < NH; h++) sv[h] = sp[h * 512 + p];
#pragma unroll
        for (int gg = 0; gg < NH; gg++) {
            unsigned long long acc = bls2[gg];
#pragma unroll
            for (int h = 0; h < NH; h++) acc = fma2(wls2[gg * NH + h], sv[h], acc);
            mv[gg] = acc;
        }
#pragma unroll
        for (int gg = 0; gg < NH; gg++) sp[gg * 512 + p] = mv[gg];
    }
    __syncthreads();

    const int lane = tid & 31, warp = tid >> 5;
    for (int gg = warp; gg < NH; gg += 8) {
        float* row = s + gg * NSEQ;
        float mx = -1e30f;
        for (int k = lane; k < NSEQ; k += 32) mx = fmaxf(mx, row[k]);
#pragma unroll
        for (int off = 16; off > 0; off >>= 1) mx = fmaxf(mx, __shfl_xor_sync(0xffffffffu, mx, off));
        float sum = 0.f;
        for (int k = lane; k < NSEQ; k += 32) {
            float e = __expf(row[k] - mx);
            row[k] = e;
            sum += e;
        }
#pragma unroll
        for (int off = 16; off > 0; off >>= 1) sum += __shfl_xor_sync(0xffffffffu, sum, off);
        const float inv = 1.f / sum;
        for (int k = lane; k < NSEQ; k += 32) row[k] *= inv;
    }
    __syncthreads();

#pragma unroll
    for (int it = 0; it < 2; it++) {
        const int p = tid + it * 256;
        unsigned long long pv[NH];
#pragma unroll
        for (int h = 0; h < NH; h++) pv[h] = sp[h * 512 + p];
#pragma unroll
        for (int gg = 0; gg < NH; gg++) {
            unsigned long long acc = bws2[gg];
#pragma unroll
            for (int h = 0; h < NH; h++) acc = fma2(wws2[gg * NH + h], pv[h], acc);
            *(unsigned long long*)(g_S + rowbase + (size_t)gg * NSEQ * NSEQ + 2 * p) = acc;
        }
    }
}

// ---------------- K4: O = P @ V per (b,h), tf32 mma, reg double-buffered ------
__global__ __launch_bounds__(256) void pv_tf32() {
    __shared__ uint32_t Ps[2][128][36];
    __shared__ uint32_t Vs[2][HD][36];

    const int bh = blockIdx.z;
    const int tid = threadIdx.x;
    const int qbase = blockIdx.x * 128;
    const float* Pg = g_S + (size_t)bh * NSEQ * NSEQ + (size_t)qbase * NSEQ;
    const float* Vg = g_v + (size_t)bh * NSEQ * HD;

    const int warp = tid >> 5, lane = tid & 31;
    const int wm = warp >> 1, wn = warp & 1;
    const int g = lane >> 2, t = lane & 3;

    const int pr = tid >> 3;
    const int pc = (tid & 7) * 4;
    const int vk = tid & 31;
    const int vd0 = tid >> 5;

    float4 pp[4];
    float pvr[6];

    float acc[2][3][4];
#pragma unroll
    for (int i = 0; i < 2; i++)
#pragma unroll
        for (int j = 0; j < 3; j++)
#pragma unroll
            for (int e = 0; e < 4; e++) acc[i][j][e] = 0.f;

#define PV_LD(kt)                                                               \
    do {                                                                        \
        _Pragma("unroll")                                                       \
        for (int j = 0; j < 4; j++)                                             \
            pp[j] = *(const float4*)(Pg + (size_t)(pr + 32 * j) * NSEQ + (kt) + pc); \
        _Pragma("unroll")                                                       \
        for (int j = 0; j < 6; j++)                                             \
            pvr[j] = Vg[(size_t)((kt) + vk) * HD + vd0 + 8 * j];                \
    } while (0)
#define PV_ST(buf)                                                              \
    do {                                                                        \
        _Pragma("unroll")                                                       \
        for (int j = 0; j < 4; j++) {                                           \
            Ps[buf][pr + 32 * j][pc + 0] = f2tf(pp[j].x);                       \
            Ps[buf][pr + 32 * j][pc + 1] = f2tf(pp[j].y);                       \
            Ps[buf][pr + 32 * j][pc + 2] = f2tf(pp[j].z);                       \
            Ps[buf][pr + 32 * j][pc + 3] = f2tf(pp[j].w);                       \
        }                                                                       \
        _Pragma("unroll")                                                       \
        for (int j = 0; j < 6; j++) Vs[buf][vd0 + 8 * j][vk] = f2tf(pvr[j]);    \
    } while (0)

    PV_LD(0);
    PV_ST(0);
    __syncthreads();

    int buf = 0;
    for (int kt = 32;; kt += 32) {
        const bool more = kt < NSEQ;
        if (more) PV_LD(kt);
#pragma unroll
        for (int ks = 0; ks < 32; ks += 8) {
            uint32_t af[2][4], bf[3][2];
#pragma unroll
            for (int mt = 0; mt < 2; mt++) {
                const int r = wm * 32 + mt * 16 + g;
                af[mt][0] = Ps[buf][r][ks + t];
                af[mt][1] = Ps[buf][r + 8][ks + t];
                af[mt][2] = Ps[buf][r][ks + t + 4];
                af[mt][3] = Ps[buf][r + 8][ks + t + 4];
            }
#pragma unroll
            for (int nt = 0; nt < 3; nt++) {
                const int n = wn * 24 + nt * 8 + g;
                bf[nt][0] = Vs[buf][n][ks + t];
                bf[nt][1] = Vs[buf][n][ks + t + 4];
            }
#pragma unroll
            for (int mt = 0; mt < 2; mt++)
#pragma unroll
                for (int nt = 0; nt < 3; nt++) mma8(acc[mt][nt], af[mt], bf[nt]);
        }
        if (!more) break;
        PV_ST(buf ^ 1);
        __syncthreads();
        buf ^= 1;
    }

    const int b = bh >> 4, h = bh & 15;
#pragma unroll
    for (int mt = 0; mt < 2; mt++)
#pragma unroll
        for (int nt = 0; nt < 3; nt++)
#pragma unroll
            for (int half = 0; half < 2; half++) {
                const int q = qbase + wm * 32 + mt * 16 + g + half * 8;
                const int d = wn * 24 + nt * 8 + 2 * t;
                float2 o = make_float2(acc[mt][nt][half * 2], acc[mt][nt][half * 2 + 1]);
                *(float2*)(g_O + (size_t)(b * NSEQ + q) * DIM + h * HD + d) = o;
            }
#undef PV_LD
#undef PV_ST
}

// ---------------- launch ------------------------------------------------------
extern "C" void kernel_launch(void* const* d_in, const int* in_sizes, int n_in,
                              void* d_out, int out_size) {
    const float* x      = (const float*)d_in[0];
    const float* w_qkv  = (const float*)d_in[1];
    const float* b_qkv  = (const float*)d_in[2];
    const float* w_l    = (const float*)d_in[3];
    const float* b_l    = (const float*)d_in[4];
    const float* w_w    = (const float*)d_in[5];
    const float* b_w    = (const float*)d_in[6];
    const float* w_proj = (const float*)d_in[7];
    const float* b_proj = (const float*)d_in[8];
    float* out = (float*)d_out;

    cudaFuncSetAttribute(mix_softmax_kernel,
                         cudaFuncAttributeMaxDynamicSharedMemorySize, 16 * NSEQ * 4);

    float* gq_p; cudaGetSymbolAddress((void**)&gq_p, g_q);
    float* gk_p; cudaGetSymbolAddress((void**)&gk_p, g_k);
    float* gO_p; cudaGetSymbolAddress((void**)&gO_p, g_O);

    // K1: QKV projection  [M=8192, N=2304, K=768]
    mm_tf32<0><<<dim3(3 * DIM / 128, BATCH * NSEQ / 128, 1), 256>>>(
        x, w_qkv, b_qkv, nullptr, DIM, 3 * DIM, 0, 0);
    // K2: logits S = q @ k^T per (b,h)  [z=128, M=N=1024, K=48]
    mm_tf32<2><<<dim3(NSEQ / 128, NSEQ / 128, BATCH * NH), 256>>>(
        gq_p, gk_p, nullptr, nullptr, HD, NSEQ,
        (size_t)NSEQ * HD, (size_t)NSEQ * HD);
    // K3: mix1 + softmax + mix2 (in place)
    mix_softmax_kernel<<<BATCH * NSEQ, 256, 16 * NSEQ * 4>>>(w_l, b_l, w_w, b_w);
    // K4: P @ V -> g_O
    pv_tf32<<<dim3(NSEQ / 128, 1, BATCH * NH), 256>>>();
    // K5: output projection  [M=8192, N=768, K=768]
    mm_tf32<1><<<dim3(DIM / 128, BATCH * NSEQ / 128, 1), 256>>>(
        gO_p, w_proj, b_proj, out, DIM, DIM, 0, 0);
}

// round 5
// speedup vs baseline: 5.4322x; 5.4309x over previous
#include <cuda_runtime.h>
#include <cstdint>

#define BATCH 8
#define NSEQ 1024
#define DIM 768
#define NH 16
#define HD 48
#define SCALE 0.14433756729740643f  /* 48^-0.5 */

// ---------------- scratch (static __device__, allocation-guard safe) ----------
__device__ __align__(256) float g_q[BATCH * NH * NSEQ * HD];
__device__ __align__(256) float g_k[BATCH * NH * NSEQ * HD];
__device__ __align__(256) float g_v[BATCH * NH * NSEQ * HD];
__device__ __align__(256) float g_S[(size_t)BATCH * NH * NSEQ * NSEQ];
__device__ __align__(256) float g_O[BATCH * NSEQ * DIM];

// ---------------- helpers -----------------------------------------------------
__device__ __forceinline__ uint32_t f2tf(float x) {
    uint32_t r;
    asm("cvt.rna.tf32.f32 %0, %1;" : "=r"(r) : "f"(x));
    return r;
}
__device__ __forceinline__ void mma8(float* c, const uint32_t* a, const uint32_t* b) {
    asm volatile(
        "mma.sync.aligned.m16n8k8.row.col.f32.tf32.tf32.f32 "
        "{%0,%1,%2,%3},{%4,%5,%6,%7},{%8,%9},{%0,%1,%2,%3};"
        : "+f"(c[0]), "+f"(c[1]), "+f"(c[2]), "+f"(c[3])
        : "r"(a[0]), "r"(a[1]), "r"(a[2]), "r"(a[3]), "r"(b[0]), "r"(b[1]));
}

#define CP16(dst_u32, src_ptr) \
    asm volatile("cp.async.cg.shared.global [%0], [%1], 16;" :: "r"(dst_u32), "l"(src_ptr))
#define CP_COMMIT() asm volatile("cp.async.commit_group;" ::)
#define CP_WAIT0()  asm volatile("cp.async.wait_group 0;" ::)

// ---------------- generic tf32 GEMM via cp.async double buffer ----------------
// Block 128x128, K-tile 16, 8 warps (2Mx4N), warp tile 64x32. K % 16 == 0.
// smem holds RAW fp32; cvt to tf32 at fragment load.
// MODE 0: qkv scatter. MODE 1: plain C+bias. MODE 2: batched store to g_S.
template <int MODE>
__global__ __launch_bounds__(256) void mm_tf32(
    const float* __restrict__ A, const float* __restrict__ W,
    const float* __restrict__ bias, float* __restrict__ C,
    int K, int Nc, size_t sA, size_t sW) {
    __shared__ float As[2][128][20];   // stride 20 -> conflict-free fragment loads
    __shared__ float Ws[2][128][20];

    const int tid = threadIdx.x;
    const int m0 = blockIdx.y * 128;
    const int n0 = blockIdx.x * 128;
    const int bz = blockIdx.z;

    const float* Ag = A + (size_t)bz * sA;
    const float* Wg = W + (size_t)bz * sW;

    const int warp = tid >> 5, lane = tid & 31;
    const int wm = warp >> 2, wn = warp & 3;
    const int g = lane >> 2, t = lane & 3;

    const int lr = tid >> 2;          // 0..63 (also row lr+64)
    const int lc = (tid & 3) * 4;     // 0,4,8,12

    const uint32_t sa = (uint32_t)__cvta_generic_to_shared(&As[0][0][0]);
    const uint32_t sw = (uint32_t)__cvta_generic_to_shared(&Ws[0][0][0]);
    const uint32_t d0 = (lr * 20 + lc) * 4;
    const uint32_t d1 = ((lr + 64) * 20 + lc) * 4;
    const uint32_t bufoff = 128 * 20 * 4;

#define MM_CP(buf, kt)                                                         \
    do {                                                                       \
        CP16(sa + (buf) * bufoff + d0, Ag + (size_t)(m0 + lr) * K + (kt) + lc);      \
        CP16(sa + (buf) * bufoff + d1, Ag + (size_t)(m0 + lr + 64) * K + (kt) + lc); \
        CP16(sw + (buf) * bufoff + d0, Wg + (size_t)(n0 + lr) * K + (kt) + lc);      \
        CP16(sw + (buf) * bufoff + d1, Wg + (size_t)(n0 + lr + 64) * K + (kt) + lc); \
        CP_COMMIT();                                                           \
    } while (0)

    float acc[4][4][4];
#pragma unroll
    for (int i = 0; i < 4; i++)
#pragma unroll
        for (int j = 0; j < 4; j++)
#pragma unroll
            for (int e = 0; e < 4; e++) acc[i][j][e] = 0.f;

    MM_CP(0, 0);
    CP_WAIT0();
    __syncthreads();

    int buf = 0;
    for (int kt = 16;; kt += 16) {
        const bool more = kt < K;
        if (more) MM_CP(buf ^ 1, kt);   // fills other buffer while we compute
#pragma unroll
        for (int ks = 0; ks < 16; ks += 8) {
            uint32_t af[4][4], bf[4][2];
#pragma unroll
            for (int mt = 0; mt < 4; mt++) {
                const int r = wm * 64 + mt * 16 + g;
                af[mt][0] = f2tf(As[buf][r][ks + t]);
                af[mt][1] = f2tf(As[buf][r + 8][ks + t]);
                af[mt][2] = f2tf(As[buf][r][ks + t + 4]);
                af[mt][3] = f2tf(As[buf][r + 8][ks + t + 4]);
            }
#pragma unroll
            for (int nt = 0; nt < 4; nt++) {
                const int n = wn * 32 + nt * 8 + g;
                bf[nt][0] = f2tf(Ws[buf][n][ks + t]);
                bf[nt][1] = f2tf(Ws[buf][n][ks + t + 4]);
            }
#pragma unroll
            for (int mt = 0; mt < 4; mt++)
#pragma unroll
                for (int nt = 0; nt < 4; nt++) mma8(acc[mt][nt], af[mt], bf[nt]);
        }
        if (!more) break;
        CP_WAIT0();
        __syncthreads();   // separates compute-on-buf from next cp into buf
        buf ^= 1;
    }

#pragma unroll
    for (int mt = 0; mt < 4; mt++) {
#pragma unroll
        for (int nt = 0; nt < 4; nt++) {
#pragma unroll
            for (int half = 0; half < 2; half++) {
                const int m = m0 + wm * 64 + mt * 16 + g + half * 8;
                const int c = n0 + wn * 32 + nt * 8 + 2 * t;
                const float v0 = acc[mt][nt][half * 2 + 0];
                const float v1 = acc[mt][nt][half * 2 + 1];
                if (MODE == 0) {
#pragma unroll
                    for (int e = 0; e < 2; e++) {
                        const int cc = c + e;
                        float v = (e ? v1 : v0) + bias[cc];
                        const int b = m >> 10, n = m & 1023;
                        const int tt = cc / DIM;
                        const int rr = cc - tt * DIM;
                        const int h = rr / HD, d = rr - h * HD;
                        const int idx = (((b * NH + h) * NSEQ) + n) * HD + d;
                        if (tt == 0)      g_q[idx] = v * SCALE;
                        else if (tt == 1) g_k[idx] = v;
                        else              g_v[idx] = v;
                    }
                } else if (MODE == 1) {
                    float2 o = make_float2(v0 + bias[c], v1 + bias[c + 1]);
                    *(float2*)(C + (size_t)m * Nc + c) = o;
                } else {
                    float* Cb = g_S + (size_t)bz * NSEQ * NSEQ;
                    *(float2*)(Cb + (size_t)m * NSEQ + c) = make_float2(v0, v1);
                }
            }
        }
    }
#undef MM_CP
}

// ---------------- K3: fused mix1 -> softmax -> mix2 (round-2 scalar form) -----
__global__ __launch_bounds__(256) void mix_softmax_kernel(
    const float* __restrict__ wl, const float* __restrict__ bl,
    const float* __restrict__ ww, const float* __restrict__ bw) {
    extern __shared__ float s[];  // [16][1024]
    __shared__ float wls[256], wws[256], bls[16], bws[16];

    const int tid = threadIdx.x;
    const int bq = blockIdx.x;
    const int b = bq >> 10, q = bq & 1023;

    wls[tid] = wl[tid];
    wws[tid] = ww[tid];
    if (tid < 16) { bls[tid] = bl[tid]; bws[tid] = bw[tid]; }

    const size_t rowbase = (size_t)(b * NH) * NSEQ * NSEQ + (size_t)q * NSEQ;
#pragma unroll
    for (int h = 0; h < NH; h++) {
        const float4* src = (const float4*)(g_S + rowbase + (size_t)h * NSEQ * NSEQ);
        ((float4*)s)[h * 256 + tid] = src[tid];
    }
    __syncthreads();

    // mix1 column-wise, in place (scalar fp32: 16 regs/array, no spill)
    for (int k = tid; k < NSEQ; k += 256) {
        float sv[NH], mv[NH];
#pragma unroll
        for (int h = 0; h < NH; h++) sv[h] = s[h * NSEQ + k];
#pragma unroll
        for (int gg = 0; gg < NH; gg++) {
            float tt = bls[gg];
#pragma unroll
            for (int h = 0; h < NH; h++) tt += wls[gg * NH + h] * sv[h];
            mv[gg] = tt;
        }
#pragma unroll
        for (int gg = 0; gg < NH; gg++) s[gg * NSEQ + k] = mv[gg];
    }
    __syncthreads();

    // softmax per head row
    const int lane = tid & 31, warp = tid >> 5;
    for (int gg = warp; gg < NH; gg += 8) {
        float* row = s + gg * NSEQ;
        float mx = -1e30f;
        for (int k = lane; k < NSEQ; k += 32) mx = fmaxf(mx, row[k]);
#pragma unroll
        for (int off = 16; off > 0; off >>= 1) mx = fmaxf(mx, __shfl_xor_sync(0xffffffffu, mx, off));
        float sum = 0.f;
        for (int k = lane; k < NSEQ; k += 32) {
            float e = __expf(row[k] - mx);
            row[k] = e;
            sum += e;
        }
#pragma unroll
        for (int off = 16; off > 0; off >>= 1) sum += __shfl_xor_sync(0xffffffffu, sum, off);
        const float inv = 1.f / sum;
        for (int k = lane; k < NSEQ; k += 32) row[k] *= inv;
    }
    __syncthreads();

    // mix2 column-wise, write back to g_S
    for (int k = tid; k < NSEQ; k += 256) {
        float pv[NH];
#pragma unroll
        for (int h = 0; h < NH; h++) pv[h] = s[h * NSEQ + k];
#pragma unroll
        for (int gg = 0; gg < NH; gg++) {
            float tt = bws[gg];
#pragma unroll
            for (int h = 0; h < NH; h++) tt += wws[gg * NH + h] * pv[h];
            g_S[rowbase + (size_t)gg * NSEQ * NSEQ + k] = tt;
        }
    }
}

// ---------------- K4: O = P @ V per (b,h), tf32 mma, reg double-buffered ------
__global__ __launch_bounds__(256) void pv_tf32() {
    __shared__ uint32_t Ps[2][128][36];
    __shared__ uint32_t Vs[2][HD][36];

    const int bh = blockIdx.z;
    const int tid = threadIdx.x;
    const int qbase = blockIdx.x * 128;
    const float* Pg = g_S + (size_t)bh * NSEQ * NSEQ + (size_t)qbase * NSEQ;
    const float* Vg = g_v + (size_t)bh * NSEQ * HD;

    const int warp = tid >> 5, lane = tid & 31;
    const int wm = warp >> 1, wn = warp & 1;
    const int g = lane >> 2, t = lane & 3;

    const int pr = tid >> 3;
    const int pc = (tid & 7) * 4;
    const int vk = tid & 31;
    const int vd0 = tid >> 5;

    float4 pp[4];
    float pvr[6];

    float acc[2][3][4];
#pragma unroll
    for (int i = 0; i < 2; i++)
#pragma unroll
        for (int j = 0; j < 3; j++)
#pragma unroll
            for (int e = 0; e < 4; e++) acc[i][j][e] = 0.f;

#define PV_LD(kt)                                                               \
    do {                                                                        \
        _Pragma("unroll")                                                       \
        for (int j = 0; j < 4; j++)                                             \
            pp[j] = *(const float4*)(Pg + (size_t)(pr + 32 * j) * NSEQ + (kt) + pc); \
        _Pragma("unroll")                                                       \
        for (int j = 0; j < 6; j++)                                             \
            pvr[j] = Vg[(size_t)((kt) + vk) * HD + vd0 + 8 * j];                \
    } while (0)
#define PV_ST(buf)                                                              \
    do {                                                                        \
        _Pragma("unroll")                                                       \
        for (int j = 0; j < 4; j++) {                                           \
            Ps[buf][pr + 32 * j][pc + 0] = f2tf(pp[j].x);                       \
            Ps[buf][pr + 32 * j][pc + 1] = f2tf(pp[j].y);                       \
            Ps[buf][pr + 32 * j][pc + 2] = f2tf(pp[j].z);                       \
            Ps[buf][pr + 32 * j][pc + 3] = f2tf(pp[j].w);                       \
        }                                                                       \
        _Pragma("unroll")                                                       \
        for (int j = 0; j < 6; j++) Vs[buf][vd0 + 8 * j][vk] = f2tf(pvr[j]);    \
    } while (0)

    PV_LD(0);
    PV_ST(0);
    __syncthreads();

    int buf = 0;
    for (int kt = 32;; kt += 32) {
        const bool more = kt < NSEQ;
        if (more) PV_LD(kt);
#pragma unroll
        for (int ks = 0; ks < 32; ks += 8) {
            uint32_t af[2][4], bf[3][2];
#pragma unroll
            for (int mt = 0; mt < 2; mt++) {
                const int r = wm * 32 + mt * 16 + g;
                af[mt][0] = Ps[buf][r][ks + t];
                af[mt][1] = Ps[buf][r + 8][ks + t];
                af[mt][2] = Ps[buf][r][ks + t + 4];
                af[mt][3] = Ps[buf][r + 8][ks + t + 4];
            }
#pragma unroll
            for (int nt = 0; nt < 3; nt++) {
                const int n = wn * 24 + nt * 8 + g;
                bf[nt][0] = Vs[buf][n][ks + t];
                bf[nt][1] = Vs[buf][n][ks + t + 4];
            }
#pragma unroll
            for (int mt = 0; mt < 2; mt++)
#pragma unroll
                for (int nt = 0; nt < 3; nt++) mma8(acc[mt][nt], af[mt], bf[nt]);
        }
        if (!more) break;
        PV_ST(buf ^ 1);
        __syncthreads();
        buf ^= 1;
    }

    const int b = bh >> 4, h = bh & 15;
#pragma unroll
    for (int mt = 0; mt < 2; mt++)
#pragma unroll
        for (int nt = 0; nt < 3; nt++)
#pragma unroll
            for (int half = 0; half < 2; half++) {
                const int q = qbase + wm * 32 + mt * 16 + g + half * 8;
                const int d = wn * 24 + nt * 8 + 2 * t;
                float2 o = make_float2(acc[mt][nt][half * 2], acc[mt][nt][half * 2 + 1]);
                *(float2*)(g_O + (size_t)(b * NSEQ + q) * DIM + h * HD + d) = o;
            }
#undef PV_LD
#undef PV_ST
}

// ---------------- launch ------------------------------------------------------
extern "C" void kernel_launch(void* const* d_in, const int* in_sizes, int n_in,
                              void* d_out, int out_size) {
    const float* x      = (const float*)d_in[0];
    const float* w_qkv  = (const float*)d_in[1];
    const float* b_qkv  = (const float*)d_in[2];
    const float* w_l    = (const float*)d_in[3];
    const float* b_l    = (const float*)d_in[4];
    const float* w_w    = (const float*)d_in[5];
    const float* b_w    = (const float*)d_in[6];
    const float* w_proj = (const float*)d_in[7];
    const float* b_proj = (const float*)d_in[8];
    float* out = (float*)d_out;

    cudaFuncSetAttribute(mix_softmax_kernel,
                         cudaFuncAttributeMaxDynamicSharedMemorySize, 16 * NSEQ * 4);

    float* gq_p; cudaGetSymbolAddress((void**)&gq_p, g_q);
    float* gk_p; cudaGetSymbolAddress((void**)&gk_p, g_k);
    float* gO_p; cudaGetSymbolAddress((void**)&gO_p, g_O);

    // K1: QKV projection  [M=8192, N=2304, K=768]
    mm_tf32<0><<<dim3(3 * DIM / 128, BATCH * NSEQ / 128, 1), 256>>>(
        x, w_qkv, b_qkv, nullptr, DIM, 3 * DIM, 0, 0);
    // K2: logits S = q @ k^T per (b,h)  [z=128, M=N=1024, K=48]
    mm_tf32<2><<<dim3(NSEQ / 128, NSEQ / 128, BATCH * NH), 256>>>(
        gq_p, gk_p, nullptr, nullptr, HD, NSEQ,
        (size_t)NSEQ * HD, (size_t)NSEQ * HD);
    // K3: mix1 + softmax + mix2 (in place)
    mix_softmax_kernel<<<BATCH * NSEQ, 256, 16 * NSEQ * 4>>>(w_l, b_l, w_w, b_w);
    // K4: P @ V -> g_O
    pv_tf32<<<dim3(NSEQ / 128, 1, BATCH * NH), 256>>>();
    // K5: output projection  [M=8192, N=768, K=768]
    mm_tf32<1><<<dim3(DIM / 128, BATCH * NSEQ / 128, 1), 256>>>(
        gO_p, w_proj, b_proj, out, DIM, DIM, 0, 0);
}

// round 6
// speedup vs baseline: 8.7759x; 1.6155x over previous
#include <cuda_runtime.h>
#include <cstdint>

#define BATCH 8
#define NSEQ 1024
#define DIM 768
#define NH 16
#define HD 48
#define SCALE 0.14433756729740643f  /* 48^-0.5 */
#define SP 1032                      /* padded smem row stride for mix kernel */

// ---------------- scratch (static __device__, allocation-guard safe) ----------
__device__ __align__(256) float g_q[BATCH * NH * NSEQ * HD];
__device__ __align__(256) float g_k[BATCH * NH * NSEQ * HD];
__device__ __align__(256) float g_v[BATCH * NH * NSEQ * HD];
__device__ __align__(256) float g_S[(size_t)BATCH * NH * NSEQ * NSEQ];
__device__ __align__(256) float g_O[BATCH * NSEQ * DIM];

// ---------------- helpers -----------------------------------------------------
__device__ __forceinline__ uint32_t f2tf(float x) {
    uint32_t r;
    asm("cvt.rna.tf32.f32 %0, %1;" : "=r"(r) : "f"(x));
    return r;
}
__device__ __forceinline__ void mma8(float* c, const uint32_t* a, const uint32_t* b) {
    asm volatile(
        "mma.sync.aligned.m16n8k8.row.col.f32.tf32.tf32.f32 "
        "{%0,%1,%2,%3},{%4,%5,%6,%7},{%8,%9},{%0,%1,%2,%3};"
        : "+f"(c[0]), "+f"(c[1]), "+f"(c[2]), "+f"(c[3])
        : "r"(a[0]), "r"(a[1]), "r"(a[2]), "r"(a[3]), "r"(b[0]), "r"(b[1]));
}

#define CP16(dst_u32, src_ptr) \
    asm volatile("cp.async.cg.shared.global [%0], [%1], 16;" :: "r"(dst_u32), "l"(src_ptr))
#define CP_COMMIT() asm volatile("cp.async.commit_group;" ::)
#define CP_WAIT0()  asm volatile("cp.async.wait_group 0;" ::)

// ---------------- generic tf32 GEMM via cp.async double buffer (UNCHANGED) ----
template <int MODE>
__global__ __launch_bounds__(256) void mm_tf32(
    const float* __restrict__ A, const float* __restrict__ W,
    const float* __restrict__ bias, float* __restrict__ C,
    int K, int Nc, size_t sA, size_t sW) {
    __shared__ float As[2][128][20];
    __shared__ float Ws[2][128][20];

    const int tid = threadIdx.x;
    const int m0 = blockIdx.y * 128;
    const int n0 = blockIdx.x * 128;
    const int bz = blockIdx.z;

    const float* Ag = A + (size_t)bz * sA;
    const float* Wg = W + (size_t)bz * sW;

    const int warp = tid >> 5, lane = tid & 31;
    const int wm = warp >> 2, wn = warp & 3;
    const int g = lane >> 2, t = lane & 3;

    const int lr = tid >> 2;
    const int lc = (tid & 3) * 4;

    const uint32_t sa = (uint32_t)__cvta_generic_to_shared(&As[0][0][0]);
    const uint32_t sw = (uint32_t)__cvta_generic_to_shared(&Ws[0][0][0]);
    const uint32_t d0 = (lr * 20 + lc) * 4;
    const uint32_t d1 = ((lr + 64) * 20 + lc) * 4;
    const uint32_t bufoff = 128 * 20 * 4;

#define MM_CP(buf, kt)                                                         \
    do {                                                                       \
        CP16(sa + (buf) * bufoff + d0, Ag + (size_t)(m0 + lr) * K + (kt) + lc);      \
        CP16(sa + (buf) * bufoff + d1, Ag + (size_t)(m0 + lr + 64) * K + (kt) + lc); \
        CP16(sw + (buf) * bufoff + d0, Wg + (size_t)(n0 + lr) * K + (kt) + lc);      \
        CP16(sw + (buf) * bufoff + d1, Wg + (size_t)(n0 + lr + 64) * K + (kt) + lc); \
        CP_COMMIT();                                                           \
    } while (0)

    float acc[4][4][4];
#pragma unroll
    for (int i = 0; i < 4; i++)
#pragma unroll
        for (int j = 0; j < 4; j++)
#pragma unroll
            for (int e = 0; e < 4; e++) acc[i][j][e] = 0.f;

    MM_CP(0, 0);
    CP_WAIT0();
    __syncthreads();

    int buf = 0;
    for (int kt = 16;; kt += 16) {
        const bool more = kt < K;
        if (more) MM_CP(buf ^ 1, kt);
#pragma unroll
        for (int ks = 0; ks < 16; ks += 8) {
            uint32_t af[4][4], bf[4][2];
#pragma unroll
            for (int mt = 0; mt < 4; mt++) {
                const int r = wm * 64 + mt * 16 + g;
                af[mt][0] = f2tf(As[buf][r][ks + t]);
                af[mt][1] = f2tf(As[buf][r + 8][ks + t]);
                af[mt][2] = f2tf(As[buf][r][ks + t + 4]);
                af[mt][3] = f2tf(As[buf][r + 8][ks + t + 4]);
            }
#pragma unroll
            for (int nt = 0; nt < 4; nt++) {
                const int n = wn * 32 + nt * 8 + g;
                bf[nt][0] = f2tf(Ws[buf][n][ks + t]);
                bf[nt][1] = f2tf(Ws[buf][n][ks + t + 4]);
            }
#pragma unroll
            for (int mt = 0; mt < 4; mt++)
#pragma unroll
                for (int nt = 0; nt < 4; nt++) mma8(acc[mt][nt], af[mt], bf[nt]);
        }
        if (!more) break;
        CP_WAIT0();
        __syncthreads();
        buf ^= 1;
    }

#pragma unroll
    for (int mt = 0; mt < 4; mt++) {
#pragma unroll
        for (int nt = 0; nt < 4; nt++) {
#pragma unroll
            for (int half = 0; half < 2; half++) {
                const int m = m0 + wm * 64 + mt * 16 + g + half * 8;
                const int c = n0 + wn * 32 + nt * 8 + 2 * t;
                const float v0 = acc[mt][nt][half * 2 + 0];
                const float v1 = acc[mt][nt][half * 2 + 1];
                if (MODE == 0) {
#pragma unroll
                    for (int e = 0; e < 2; e++) {
                        const int cc = c + e;
                        float v = (e ? v1 : v0) + bias[cc];
                        const int b = m >> 10, n = m & 1023;
                        const int tt = cc / DIM;
                        const int rr = cc - tt * DIM;
                        const int h = rr / HD, d = rr - h * HD;
                        const int idx = (((b * NH + h) * NSEQ) + n) * HD + d;
                        if (tt == 0)      g_q[idx] = v * SCALE;
                        else if (tt == 1) g_k[idx] = v;
                        else              g_v[idx] = v;
                    }
                } else if (MODE == 1) {
                    float2 o = make_float2(v0 + bias[c], v1 + bias[c + 1]);
                    *(float2*)(C + (size_t)m * Nc + c) = o;
                } else {
                    float* Cb = g_S + (size_t)bz * NSEQ * NSEQ;
                    *(float2*)(Cb + (size_t)m * NSEQ + c) = make_float2(v0, v1);
                }
            }
        }
    }
#undef MM_CP
}

// ---------------- K3: mix1 -> softmax -> mix2; mixes on tensor cores ----------
// One block per (b,q). s[16][SP]. Each warp owns a 128-col stripe for the mixes.
__global__ __launch_bounds__(256) void mix_softmax_kernel(
    const float* __restrict__ wl, const float* __restrict__ bl,
    const float* __restrict__ ww, const float* __restrict__ bw) {
    extern __shared__ float s[];  // [16][SP]

    const int tid = threadIdx.x;
    const int lane = tid & 31, warp = tid >> 5;
    const int ar = lane >> 2;     // mma row group 0..7
    const int ac = lane & 3;      // mma col-in-group 0..3
    const int bq = blockIdx.x;
    const int b = bq >> 10, q = bq & 1023;

    // A fragments for W_l and W_w: A[m=g][k=h], khalf kh covers h = kh*8 + k.
    uint32_t la[2][4], wa[2][4];
#pragma unroll
    for (int kh = 0; kh < 2; kh++) {
        la[kh][0] = f2tf(wl[ar * NH + kh * 8 + ac]);
        la[kh][1] = f2tf(wl[(ar + 8) * NH + kh * 8 + ac]);
        la[kh][2] = f2tf(wl[ar * NH + kh * 8 + ac + 4]);
        la[kh][3] = f2tf(wl[(ar + 8) * NH + kh * 8 + ac + 4]);
        wa[kh][0] = f2tf(ww[ar * NH + kh * 8 + ac]);
        wa[kh][1] = f2tf(ww[(ar + 8) * NH + kh * 8 + ac]);
        wa[kh][2] = f2tf(ww[ar * NH + kh * 8 + ac + 4]);
        wa[kh][3] = f2tf(ww[(ar + 8) * NH + kh * 8 + ac + 4]);
    }
    const float bl0 = bl[ar], bl1 = bl[ar + 8];
    const float bw0 = bw[ar], bw1 = bw[ar + 8];

    const size_t rowbase = (size_t)(b * NH) * NSEQ * NSEQ + (size_t)q * NSEQ;
#pragma unroll
    for (int h = 0; h < NH; h++) {
        const float4* src = (const float4*)(g_S + rowbase + (size_t)h * NSEQ * NSEQ);
        ((float4*)(s + h * SP))[tid] = src[tid];
    }
    __syncthreads();

    // ---- mix1 via mma (in place; warp owns cols [warp*128, warp*128+128)) ----
#pragma unroll 4
    for (int c0 = warp * 128; c0 < warp * 128 + 128; c0 += 8) {
        uint32_t bf0[2], bf1[2];
        bf0[0] = f2tf(s[ac * SP + c0 + ar]);
        bf0[1] = f2tf(s[(ac + 4) * SP + c0 + ar]);
        bf1[0] = f2tf(s[(8 + ac) * SP + c0 + ar]);
        bf1[1] = f2tf(s[(12 + ac) * SP + c0 + ar]);
        float c[4] = {bl0, bl0, bl1, bl1};
        mma8(c, la[0], bf0);
        mma8(c, la[1], bf1);
        __syncwarp();  // all reads of this col-group done before overwrite
        *(float2*)(s + ar * SP + c0 + 2 * ac) = make_float2(c[0], c[1]);
        *(float2*)(s + (ar + 8) * SP + c0 + 2 * ac) = make_float2(c[2], c[3]);
        __syncwarp();
    }
    __syncthreads();

    // ---- softmax per head row ----
    for (int gg = warp; gg < NH; gg += 8) {
        float* row = s + gg * SP;
        float mx = -1e30f;
        for (int k = lane; k < NSEQ; k += 32) mx = fmaxf(mx, row[k]);
#pragma unroll
        for (int off = 16; off > 0; off >>= 1) mx = fmaxf(mx, __shfl_xor_sync(0xffffffffu, mx, off));
        float sum = 0.f;
        for (int k = lane; k < NSEQ; k += 32) {
            float e = __expf(row[k] - mx);
            row[k] = e;
            sum += e;
        }
#pragma unroll
        for (int off = 16; off > 0; off >>= 1) sum += __shfl_xor_sync(0xffffffffu, sum, off);
        const float inv = 1.f / sum;
        for (int k = lane; k < NSEQ; k += 32) row[k] *= inv;
    }
    __syncthreads();

    // ---- mix2 via mma, write to g_S ----
#pragma unroll 4
    for (int c0 = warp * 128; c0 < warp * 128 + 128; c0 += 8) {
        uint32_t bf0[2], bf1[2];
        bf0[0] = f2tf(s[ac * SP + c0 + ar]);
        bf0[1] = f2tf(s[(ac + 4) * SP + c0 + ar]);
        bf1[0] = f2tf(s[(8 + ac) * SP + c0 + ar]);
        bf1[1] = f2tf(s[(12 + ac) * SP + c0 + ar]);
        float c[4] = {bw0, bw0, bw1, bw1};
        mma8(c, wa[0], bf0);
        mma8(c, wa[1], bf1);
        *(float2*)(g_S + rowbase + (size_t)ar * NSEQ * NSEQ + c0 + 2 * ac) =
            make_float2(c[0], c[1]);
        *(float2*)(g_S + rowbase + (size_t)(ar + 8) * NSEQ * NSEQ + c0 + 2 * ac) =
            make_float2(c[2], c[3]);
    }
}

// ---------------- K4: O = P @ V per (b,h), tf32 mma + cp.async ----------------
#define PS_STRIDE 36
#define VS_STRIDE 56
__global__ __launch_bounds__(256) void pv_tf32() {
    __shared__ float Ps[2][128][PS_STRIDE];
    __shared__ float Vs[2][32][VS_STRIDE];

    const int bh = blockIdx.z;
    const int tid = threadIdx.x;
    const int qbase = blockIdx.x * 128;
    const float* Pg = g_S + (size_t)bh * NSEQ * NSEQ + (size_t)qbase * NSEQ;
    const float* Vg = g_v + (size_t)bh * NSEQ * HD;

    const int warp = tid >> 5, lane = tid & 31;
    const int wm = warp >> 1, wn = warp & 1;
    const int g = lane >> 2, t = lane & 3;

    const uint32_t psa = (uint32_t)__cvta_generic_to_shared(&Ps[0][0][0]);
    const uint32_t vsa = (uint32_t)__cvta_generic_to_shared(&Vs[0][0][0]);
    const uint32_t PSZ = 128 * PS_STRIDE * 4;
    const uint32_t VSZ = 32 * VS_STRIDE * 4;

#define PV_CP(buf, kt)                                                          \
    do {                                                                        \
        _Pragma("unroll")                                                       \
        for (int j = 0; j < 4; j++) {                                           \
            const int i = tid + 256 * j;                                        \
            const int r = i >> 3, c = (i & 7) * 4;                              \
            CP16(psa + (buf) * PSZ + (uint32_t)(r * PS_STRIDE + c) * 4,         \
                 Pg + (size_t)r * NSEQ + (kt) + c);                             \
        }                                                                       \
        _Pragma("unroll")                                                       \
        for (int j = 0; j < 2; j++) {                                           \
            const int i = tid + 256 * j;                                        \
            if (i < 384) {                                                      \
                const int k = i / 12, d = (i % 12) * 4;                         \
                CP16(vsa + (buf) * VSZ + (uint32_t)(k * VS_STRIDE + d) * 4,     \
                     Vg + (size_t)((kt) + k) * HD + d);                         \
            }                                                                   \
        }                                                                       \
        CP_COMMIT();                                                            \
    } while (0)

    float acc[2][3][4];
#pragma unroll
    for (int i = 0; i < 2; i++)
#pragma unroll
        for (int j = 0; j < 3; j++)
#pragma unroll
            for (int e = 0; e < 4; e++) acc[i][j][e] = 0.f;

    PV_CP(0, 0);
    CP_WAIT0();
    __syncthreads();

    int buf = 0;
    for (int kt = 32;; kt += 32) {
        const bool more = kt < NSEQ;
        if (more) PV_CP(buf ^ 1, kt);
#pragma unroll
        for (int ks = 0; ks < 32; ks += 8) {
            uint32_t af[2][4], bf[3][2];
#pragma unroll
            for (int mt = 0; mt < 2; mt++) {
                const int r = wm * 32 + mt * 16 + g;
                af[mt][0] = f2tf(Ps[buf][r][ks + t]);
                af[mt][1] = f2tf(Ps[buf][r + 8][ks + t]);
                af[mt][2] = f2tf(Ps[buf][r][ks + t + 4]);
                af[mt][3] = f2tf(Ps[buf][r + 8][ks + t + 4]);
            }
#pragma unroll
            for (int nt = 0; nt < 3; nt++) {
                const int n = wn * 24 + nt * 8 + g;
                bf[nt][0] = f2tf(Vs[buf][ks + t][n]);
                bf[nt][1] = f2tf(Vs[buf][ks + t + 4][n]);
            }
#pragma unroll
            for (int mt = 0; mt < 2; mt++)
#pragma unroll
                for (int nt = 0; nt < 3; nt++) mma8(acc[mt][nt], af[mt], bf[nt]);
        }
        if (!more) break;
        CP_WAIT0();
        __syncthreads();
        buf ^= 1;
    }

    const int b = bh >> 4, h = bh & 15;
#pragma unroll
    for (int mt = 0; mt < 2; mt++)
#pragma unroll
        for (int nt = 0; nt < 3; nt++)
#pragma unroll
            for (int half = 0; half < 2; half++) {
                const int q = qbase + wm * 32 + mt * 16 + g + half * 8;
                const int d = wn * 24 + nt * 8 + 2 * t;
                float2 o = make_float2(acc[mt][nt][half * 2], acc[mt][nt][half * 2 + 1]);
                *(float2*)(g_O + (size_t)(b * NSEQ + q) * DIM + h * HD + d) = o;
            }
#undef PV_CP
}

// ---------------- launch ------------------------------------------------------
extern "C" void kernel_launch(void* const* d_in, const int* in_sizes, int n_in,
                              void* d_out, int out_size) {
    const float* x      = (const float*)d_in[0];
    const float* w_qkv  = (const float*)d_in[1];
    const float* b_qkv  = (const float*)d_in[2];
    const float* w_l    = (const float*)d_in[3];
    const float* b_l    = (const float*)d_in[4];
    const float* w_w    = (const float*)d_in[5];
    const float* b_w    = (const float*)d_in[6];
    const float* w_proj = (const float*)d_in[7];
    const float* b_proj = (const float*)d_in[8];
    float* out = (float*)d_out;

    cudaFuncSetAttribute(mix_softmax_kernel,
                         cudaFuncAttributeMaxDynamicSharedMemorySize, NH * SP * 4);

    float* gq_p; cudaGetSymbolAddress((void**)&gq_p, g_q);
    float* gk_p; cudaGetSymbolAddress((void**)&gk_p, g_k);
    float* gO_p; cudaGetSymbolAddress((void**)&gO_p, g_O);

    // K1: QKV projection  [M=8192, N=2304, K=768]
    mm_tf32<0><<<dim3(3 * DIM / 128, BATCH * NSEQ / 128, 1), 256>>>(
        x, w_qkv, b_qkv, nullptr, DIM, 3 * DIM, 0, 0);
    // K2: logits S = q @ k^T per (b,h)  [z=128, M=N=1024, K=48]
    mm_tf32<2><<<dim3(NSEQ / 128, NSEQ / 128, BATCH * NH), 256>>>(
        gq_p, gk_p, nullptr, nullptr, HD, NSEQ,
        (size_t)NSEQ * HD, (size_t)NSEQ * HD);
    // K3: mix1 + softmax + mix2 (in place)
    mix_softmax_kernel<<<BATCH * NSEQ, 256, NH * SP * 4>>>(w_l, b_l, w_w, b_w);
    // K4: P @ V -> g_O
    pv_tf32<<<dim3(NSEQ / 128, 1, BATCH * NH), 256>>>();
    // K5: output projection  [M=8192, N=768, K=768]
    mm_tf32<1><<<dim3(DIM / 128, BATCH * NSEQ / 128, 1), 256>>>(
        gO_p, w_proj, b_proj, out, DIM, DIM, 0, 0);
}

// round 7
// speedup vs baseline: 10.7767x; 1.2280x over previous
#include <cuda_runtime.h>
#include <cuda_fp16.h>
#include <cstdint>

#define BATCH 8
#define NSEQ 1024
#define DIM 768
#define NH 16
#define HD 48
#define SCALE 0.14433756729740643f  /* 48^-0.5 */
#define SP 1032                      /* padded fp32 smem row stride for mix kernel */

// ---------------- scratch (static __device__, allocation-guard safe) ----------
__device__ __align__(256) __half g_q[BATCH * NH * NSEQ * HD];       // [b][h][n][d] (pre-scaled)
__device__ __align__(256) __half g_k[BATCH * NH * NSEQ * HD];       // [b][h][n][d]
__device__ __align__(256) __half g_v[BATCH * NH * HD * NSEQ];       // [b][h][d][n]  TRANSPOSED
__device__ __align__(256) __half g_S[(size_t)BATCH * NH * NSEQ * NSEQ];  // logits -> probs
__device__ __align__(256) float  g_O[BATCH * NSEQ * DIM];           // attn out pre-proj (fp32)

// ---------------- helpers -----------------------------------------------------
__device__ __forceinline__ uint32_t f2tf(float x) {
    uint32_t r;
    asm("cvt.rna.tf32.f32 %0, %1;" : "=r"(r) : "f"(x));
    return r;
}
__device__ __forceinline__ void mma8(float* c, const uint32_t* a, const uint32_t* b) {
    asm volatile(
        "mma.sync.aligned.m16n8k8.row.col.f32.tf32.tf32.f32 "
        "{%0,%1,%2,%3},{%4,%5,%6,%7},{%8,%9},{%0,%1,%2,%3};"
        : "+f"(c[0]), "+f"(c[1]), "+f"(c[2]), "+f"(c[3])
        : "r"(a[0]), "r"(a[1]), "r"(a[2]), "r"(a[3]), "r"(b[0]), "r"(b[1]));
}
__device__ __forceinline__ void mma16h(float* c, const uint32_t* a, const uint32_t* b) {
    asm volatile(
        "mma.sync.aligned.m16n8k16.row.col.f32.f16.f16.f32 "
        "{%0,%1,%2,%3},{%4,%5,%6,%7},{%8,%9},{%0,%1,%2,%3};"
        : "+f"(c[0]), "+f"(c[1]), "+f"(c[2]), "+f"(c[3])
        : "r"(a[0]), "r"(a[1]), "r"(a[2]), "r"(a[3]), "r"(b[0]), "r"(b[1]));
}

#define CP16(dst_u32, src_ptr) \
    asm volatile("cp.async.cg.shared.global [%0], [%1], 16;" :: "r"(dst_u32), "l"(src_ptr))
#define CP_COMMIT() asm volatile("cp.async.commit_group;" ::)
#define CP_WAIT0()  asm volatile("cp.async.wait_group 0;" ::)

// ---------------- mm_tf32: qkv (MODE 0) & proj (MODE 1), cp.async dbuf --------
template <int MODE>
__global__ __launch_bounds__(256) void mm_tf32(
    const float* __restrict__ A, const float* __restrict__ W,
    const float* __restrict__ bias, float* __restrict__ C, int K, int Nc) {
    __shared__ float As[2][128][20];
    __shared__ float Ws[2][128][20];

    const int tid = threadIdx.x;
    const int m0 = blockIdx.y * 128;
    const int n0 = blockIdx.x * 128;

    const float* Ag = (MODE == 1) ? g_O : A;
    const float* Wg = W;

    const int warp = tid >> 5, lane = tid & 31;
    const int wm = warp >> 2, wn = warp & 3;
    const int g = lane >> 2, t = lane & 3;

    const int lr = tid >> 2;
    const int lc = (tid & 3) * 4;

    const uint32_t sa = (uint32_t)__cvta_generic_to_shared(&As[0][0][0]);
    const uint32_t sw = (uint32_t)__cvta_generic_to_shared(&Ws[0][0][0]);
    const uint32_t d0 = (lr * 20 + lc) * 4;
    const uint32_t d1 = ((lr + 64) * 20 + lc) * 4;
    const uint32_t bufoff = 128 * 20 * 4;

#define MM_CP(buf, kt)                                                         \
    do {                                                                       \
        CP16(sa + (buf) * bufoff + d0, Ag + (size_t)(m0 + lr) * K + (kt) + lc);      \
        CP16(sa + (buf) * bufoff + d1, Ag + (size_t)(m0 + lr + 64) * K + (kt) + lc); \
        CP16(sw + (buf) * bufoff + d0, Wg + (size_t)(n0 + lr) * K + (kt) + lc);      \
        CP16(sw + (buf) * bufoff + d1, Wg + (size_t)(n0 + lr + 64) * K + (kt) + lc); \
        CP_COMMIT();                                                           \
    } while (0)

    float acc[4][4][4];
#pragma unroll
    for (int i = 0; i < 4; i++)
#pragma unroll
        for (int j = 0; j < 4; j++)
#pragma unroll
            for (int e = 0; e < 4; e++) acc[i][j][e] = 0.f;

    MM_CP(0, 0);
    CP_WAIT0();
    __syncthreads();

    int buf = 0;
    for (int kt = 16;; kt += 16) {
        const bool more = kt < K;
        if (more) MM_CP(buf ^ 1, kt);
#pragma unroll
        for (int ks = 0; ks < 16; ks += 8) {
            uint32_t af[4][4], bf[4][2];
#pragma unroll
            for (int mt = 0; mt < 4; mt++) {
                const int r = wm * 64 + mt * 16 + g;
                af[mt][0] = f2tf(As[buf][r][ks + t]);
                af[mt][1] = f2tf(As[buf][r + 8][ks + t]);
                af[mt][2] = f2tf(As[buf][r][ks + t + 4]);
                af[mt][3] = f2tf(As[buf][r + 8][ks + t + 4]);
            }
#pragma unroll
            for (int nt = 0; nt < 4; nt++) {
                const int n = wn * 32 + nt * 8 + g;
                bf[nt][0] = f2tf(Ws[buf][n][ks + t]);
                bf[nt][1] = f2tf(Ws[buf][n][ks + t + 4]);
            }
#pragma unroll
            for (int mt = 0; mt < 4; mt++)
#pragma unroll
                for (int nt = 0; nt < 4; nt++) mma8(acc[mt][nt], af[mt], bf[nt]);
        }
        if (!more) break;
        CP_WAIT0();
        __syncthreads();
        buf ^= 1;
    }

#pragma unroll
    for (int mt = 0; mt < 4; mt++) {
#pragma unroll
        for (int nt = 0; nt < 4; nt++) {
#pragma unroll
            for (int half = 0; half < 2; half++) {
                const int m = m0 + wm * 64 + mt * 16 + g + half * 8;
                const int c = n0 + wn * 32 + nt * 8 + 2 * t;
                const float v0 = acc[mt][nt][half * 2 + 0];
                const float v1 = acc[mt][nt][half * 2 + 1];
                if (MODE == 0) {
#pragma unroll
                    for (int e = 0; e < 2; e++) {
                        const int cc = c + e;
                        float v = (e ? v1 : v0) + bias[cc];
                        const int b = m >> 10, n = m & 1023;
                        const int tt = cc / DIM;
                        const int rr = cc - tt * DIM;
                        const int h = rr / HD, d = rr - h * HD;
                        const int bh = b * NH + h;
                        if (tt == 0)
                            g_q[((size_t)bh * NSEQ + n) * HD + d] = __float2half(v * SCALE);
                        else if (tt == 1)
                            g_k[((size_t)bh * NSEQ + n) * HD + d] = __float2half(v);
                        else
                            g_v[((size_t)bh * HD + d) * NSEQ + n] = __float2half(v);
                    }
                } else {
                    float2 o = make_float2(v0 + bias[c], v1 + bias[c + 1]);
                    *(float2*)(C + (size_t)m * Nc + c) = o;
                }
            }
        }
    }
#undef MM_CP
}

// ---------------- K2: S = q @ k^T per (b,h), fp16 mma, K=48 single-shot -------
__global__ __launch_bounds__(256) void qk_fp16() {
    __shared__ __half Qs[128][56];   // stride 56 halfs: word 28g+t all-distinct
    __shared__ __half Ks[128][56];

    const int tid = threadIdx.x;
    const int bh = blockIdx.z;
    const int q0 = blockIdx.y * 128;
    const int k0 = blockIdx.x * 128;

    const __half* Qg = g_q + (size_t)bh * NSEQ * HD;
    const __half* Kg = g_k + (size_t)bh * NSEQ * HD;

    const uint32_t sq = (uint32_t)__cvta_generic_to_shared(&Qs[0][0]);
    const uint32_t sk = (uint32_t)__cvta_generic_to_shared(&Ks[0][0]);

#pragma unroll
    for (int j = 0; j < 3; j++) {
        const int i = tid + 256 * j;        // 0..767 = 128 rows x 6 chunks
        const int r = i / 6, c = (i % 6) * 8;
        CP16(sq + (uint32_t)(r * 56 + c) * 2, Qg + (size_t)(q0 + r) * HD + c);
        CP16(sk + (uint32_t)(r * 56 + c) * 2, Kg + (size_t)(k0 + r) * HD + c);
    }
    CP_COMMIT();
    CP_WAIT0();
    __syncthreads();

    const int warp = tid >> 5, lane = tid & 31;
    const int wm = warp >> 2, wn = warp & 3;
    const int g = lane >> 2, t = lane & 3;

    float acc[4][4][4];
#pragma unroll
    for (int i = 0; i < 4; i++)
#pragma unroll
        for (int j = 0; j < 4; j++)
#pragma unroll
            for (int e = 0; e < 4; e++) acc[i][j][e] = 0.f;

#pragma unroll
    for (int ks = 0; ks < 3; ks++) {     // K = 48 = 3 x k16
        const int kb = ks * 16 + 2 * t;
        uint32_t af[4][4], bf[4][2];
#pragma unroll
        for (int mt = 0; mt < 4; mt++) {
            const int r = wm * 64 + mt * 16 + g;
            af[mt][0] = *(const uint32_t*)&Qs[r][kb];
            af[mt][1] = *(const uint32_t*)&Qs[r + 8][kb];
            af[mt][2] = *(const uint32_t*)&Qs[r][kb + 8];
            af[mt][3] = *(const uint32_t*)&Qs[r + 8][kb + 8];
        }
#pragma unroll
        for (int nt = 0; nt < 4; nt++) {
            const int n = wn * 32 + nt * 8 + g;
            bf[nt][0] = *(const uint32_t*)&Ks[n][kb];
            bf[nt][1] = *(const uint32_t*)&Ks[n][kb + 8];
        }
#pragma unroll
        for (int mt = 0; mt < 4; mt++)
#pragma unroll
            for (int nt = 0; nt < 4; nt++) mma16h(acc[mt][nt], af[mt], bf[nt]);
    }

    __half* Sg = g_S + (size_t)bh * NSEQ * NSEQ;
#pragma unroll
    for (int mt = 0; mt < 4; mt++)
#pragma unroll
        for (int nt = 0; nt < 4; nt++)
#pragma unroll
            for (int half = 0; half < 2; half++) {
                const int m = q0 + wm * 64 + mt * 16 + g + half * 8;
                const int c = k0 + wn * 32 + nt * 8 + 2 * t;
                *(__half2*)(Sg + (size_t)m * NSEQ + c) =
                    __floats2half2_rn(acc[mt][nt][half * 2], acc[mt][nt][half * 2 + 1]);
            }
}

// ---------------- K3: mix1 -> softmax -> mix2; fp16 I/O, mma mixes ------------
__global__ __launch_bounds__(256) void mix_softmax_kernel(
    const float* __restrict__ wl, const float* __restrict__ bl,
    const float* __restrict__ ww, const float* __restrict__ bw) {
    extern __shared__ float s[];  // [16][SP]

    const int tid = threadIdx.x;
    const int lane = tid & 31, warp = tid >> 5;
    const int ar = lane >> 2;
    const int ac = lane & 3;
    const int bq = blockIdx.x;
    const int b = bq >> 10, q = bq & 1023;

    uint32_t la[2][4], wa[2][4];
#pragma unroll
    for (int kh = 0; kh < 2; kh++) {
        la[kh][0] = f2tf(wl[ar * NH + kh * 8 + ac]);
        la[kh][1] = f2tf(wl[(ar + 8) * NH + kh * 8 + ac]);
        la[kh][2] = f2tf(wl[ar * NH + kh * 8 + ac + 4]);
        la[kh][3] = f2tf(wl[(ar + 8) * NH + kh * 8 + ac + 4]);
        wa[kh][0] = f2tf(ww[ar * NH + kh * 8 + ac]);
        wa[kh][1] = f2tf(ww[(ar + 8) * NH + kh * 8 + ac]);
        wa[kh][2] = f2tf(ww[ar * NH + kh * 8 + ac + 4]);
        wa[kh][3] = f2tf(ww[(ar + 8) * NH + kh * 8 + ac + 4]);
    }
    const float bl0 = bl[ar], bl1 = bl[ar + 8];
    const float bw0 = bw[ar], bw1 = bw[ar + 8];

    const size_t rowbase = (size_t)(b * NH) * NSEQ * NSEQ + (size_t)q * NSEQ;
#pragma unroll
    for (int h = 0; h < NH; h++) {
        const __half2* src = (const __half2*)(g_S + rowbase + (size_t)h * NSEQ * NSEQ);
#pragma unroll
        for (int j = 0; j < 2; j++) {
            const int i = tid + 256 * j;
            const float2 f = __half22float2(src[i]);
            s[h * SP + 2 * i] = f.x;
            s[h * SP + 2 * i + 1] = f.y;
        }
    }
    __syncthreads();

    // mix1 via mma, in place
#pragma unroll 4
    for (int c0 = warp * 128; c0 < warp * 128 + 128; c0 += 8) {
        uint32_t bf0[2], bf1[2];
        bf0[0] = f2tf(s[ac * SP + c0 + ar]);
        bf0[1] = f2tf(s[(ac + 4) * SP + c0 + ar]);
        bf1[0] = f2tf(s[(8 + ac) * SP + c0 + ar]);
        bf1[1] = f2tf(s[(12 + ac) * SP + c0 + ar]);
        float c[4] = {bl0, bl0, bl1, bl1};
        mma8(c, la[0], bf0);
        mma8(c, la[1], bf1);
        __syncwarp();
        *(float2*)(s + ar * SP + c0 + 2 * ac) = make_float2(c[0], c[1]);
        *(float2*)(s + (ar + 8) * SP + c0 + 2 * ac) = make_float2(c[2], c[3]);
        __syncwarp();
    }
    __syncthreads();

    // softmax per head row
    for (int gg = warp; gg < NH; gg += 8) {
        float* row = s + gg * SP;
        float mx = -1e30f;
        for (int k = lane; k < NSEQ; k += 32) mx = fmaxf(mx, row[k]);
#pragma unroll
        for (int off = 16; off > 0; off >>= 1) mx = fmaxf(mx, __shfl_xor_sync(0xffffffffu, mx, off));
        float sum = 0.f;
        for (int k = lane; k < NSEQ; k += 32) {
            float e = __expf(row[k] - mx);
            row[k] = e;
            sum += e;
        }
#pragma unroll
        for (int off = 16; off > 0; off >>= 1) sum += __shfl_xor_sync(0xffffffffu, sum, off);
        const float inv = 1.f / sum;
        for (int k = lane; k < NSEQ; k += 32) row[k] *= inv;
    }
    __syncthreads();

    // mix2 via mma, write fp16 to g_S
#pragma unroll 4
    for (int c0 = warp * 128; c0 < warp * 128 + 128; c0 += 8) {
        uint32_t bf0[2], bf1[2];
        bf0[0] = f2tf(s[ac * SP + c0 + ar]);
        bf0[1] = f2tf(s[(ac + 4) * SP + c0 + ar]);
        bf1[0] = f2tf(s[(8 + ac) * SP + c0 + ar]);
        bf1[1] = f2tf(s[(12 + ac) * SP + c0 + ar]);
        float c[4] = {bw0, bw0, bw1, bw1};
        mma8(c, wa[0], bf0);
        mma8(c, wa[1], bf1);
        *(__half2*)(g_S + rowbase + (size_t)ar * NSEQ * NSEQ + c0 + 2 * ac) =
            __floats2half2_rn(c[0], c[1]);
        *(__half2*)(g_S + rowbase + (size_t)(ar + 8) * NSEQ * NSEQ + c0 + 2 * ac) =
            __floats2half2_rn(c[2], c[3]);
    }
}

// ---------------- K4: O = P @ V per (b,h), fp16 mma + cp.async dbuf -----------
__global__ __launch_bounds__(256) void pv_fp16() {
    __shared__ __half Ps[2][128][40];   // word 20g+t all-distinct -> conflict-free
    __shared__ __half Vs[2][HD][40];

    const int bh = blockIdx.z;
    const int tid = threadIdx.x;
    const int qbase = blockIdx.x * 128;
    const __half* Pg = g_S + (size_t)bh * NSEQ * NSEQ + (size_t)qbase * NSEQ;
    const __half* Vg = g_v + (size_t)bh * HD * NSEQ;   // [d][n]

    const int warp = tid >> 5, lane = tid & 31;
    const int wm = warp >> 1, wn = warp & 1;
    const int g = lane >> 2, t = lane & 3;

    const uint32_t psa = (uint32_t)__cvta_generic_to_shared(&Ps[0][0][0]);
    const uint32_t vsa = (uint32_t)__cvta_generic_to_shared(&Vs[0][0][0]);
    const uint32_t PSZ = 128 * 40 * 2;
    const uint32_t VSZ = HD * 40 * 2;

#define PV_CP(buf, kt)                                                          \
    do {                                                                        \
        _Pragma("unroll")                                                       \
        for (int j = 0; j < 2; j++) {                                           \
            const int i = tid + 256 * j;          /* 0..511: 128 rows x 4 */    \
            const int r = i >> 2, c = (i & 3) * 8;                              \
            CP16(psa + (buf) * PSZ + (uint32_t)(r * 40 + c) * 2,                \
                 Pg + (size_t)r * NSEQ + (kt) + c);                             \
        }                                                                       \
        if (tid < 192) {                          /* 48 rows x 4 */             \
            const int d = tid >> 2, c = (tid & 3) * 8;                          \
            CP16(vsa + (buf) * VSZ + (uint32_t)(d * 40 + c) * 2,                \
                 Vg + (size_t)d * NSEQ + (kt) + c);                             \
        }                                                                       \
        CP_COMMIT();                                                            \
    } while (0)

    float acc[2][3][4];
#pragma unroll
    for (int i = 0; i < 2; i++)
#pragma unroll
        for (int j = 0; j < 3; j++)
#pragma unroll
            for (int e = 0; e < 4; e++) acc[i][j][e] = 0.f;

    PV_CP(0, 0);
    CP_WAIT0();
    __syncthreads();

    int buf = 0;
    for (int kt = 32;; kt += 32) {
        const bool more = kt < NSEQ;
        if (more) PV_CP(buf ^ 1, kt);
#pragma unroll
        for (int ks = 0; ks < 2; ks++) {
            const int kb = ks * 16 + 2 * t;
            uint32_t af[2][4], bf[3][2];
#pragma unroll
            for (int mt = 0; mt < 2; mt++) {
                const int r = wm * 32 + mt * 16 + g;
                af[mt][0] = *(const uint32_t*)&Ps[buf][r][kb];
                af[mt][1] = *(const uint32_t*)&Ps[buf][r + 8][kb];
                af[mt][2] = *(const uint32_t*)&Ps[buf][r][kb + 8];
                af[mt][3] = *(const uint32_t*)&Ps[buf][r + 8][kb + 8];
            }
#pragma unroll
            for (int nt = 0; nt < 3; nt++) {
                const int n = wn * 24 + nt * 8 + g;
                bf[nt][0] = *(const uint32_t*)&Vs[buf][n][kb];
                bf[nt][1] = *(const uint32_t*)&Vs[buf][n][kb + 8];
            }
#pragma unroll
            for (int mt = 0; mt < 2; mt++)
#pragma unroll
                for (int nt = 0; nt < 3; nt++) mma16h(acc[mt][nt], af[mt], bf[nt]);
        }
        if (!more) break;
        CP_WAIT0();
        __syncthreads();
        buf ^= 1;
    }

    const int b = bh >> 4, h = bh & 15;
#pragma unroll
    for (int mt = 0; mt < 2; mt++)
#pragma unroll
        for (int nt = 0; nt < 3; nt++)
#pragma unroll
            for (int half = 0; half < 2; half++) {
                const int q = qbase + wm * 32 + mt * 16 + g + half * 8;
                const int d = wn * 24 + nt * 8 + 2 * t;
                float2 o = make_float2(acc[mt][nt][half * 2], acc[mt][nt][half * 2 + 1]);
                *(float2*)(g_O + (size_t)(b * NSEQ + q) * DIM + h * HD + d) = o;
            }
#undef PV_CP
}

// ---------------- launch ------------------------------------------------------
extern "C" void kernel_launch(void* const* d_in, const int* in_sizes, int n_in,
                              void* d_out, int out_size) {
    const float* x      = (const float*)d_in[0];
    const float* w_qkv  = (const float*)d_in[1];
    const float* b_qkv  = (const float*)d_in[2];
    const float* w_l    = (const float*)d_in[3];
    const float* b_l    = (const float*)d_in[4];
    const float* w_w    = (const float*)d_in[5];
    const float* b_w    = (const float*)d_in[6];
    const float* w_proj = (const float*)d_in[7];
    const float* b_proj = (const float*)d_in[8];
    float* out = (float*)d_out;

    cudaFuncSetAttribute(mix_softmax_kernel,
                         cudaFuncAttributeMaxDynamicSharedMemorySize, NH * SP * 4);

    // K1: QKV projection  [M=8192, N=2304, K=768] -> fp16 q/k/v (v transposed)
    mm_tf32<0><<<dim3(3 * DIM / 128, BATCH * NSEQ / 128), 256>>>(
        x, w_qkv, b_qkv, nullptr, DIM, 3 * DIM);
    // K2: logits S = q @ k^T per (b,h), fp16
    qk_fp16<<<dim3(NSEQ / 128, NSEQ / 128, BATCH * NH), 256>>>();
    // K3: mix1 + softmax + mix2 (in place, fp16 I/O)
    mix_softmax_kernel<<<BATCH * NSEQ, 256, NH * SP * 4>>>(w_l, b_l, w_w, b_w);
    // K4: P @ V -> g_O (fp16 mma)
    pv_fp16<<<dim3(NSEQ / 128, 1, BATCH * NH), 256>>>();
    // K5: output projection  [M=8192, N=768, K=768]
    mm_tf32<1><<<dim3(DIM / 128, BATCH * NSEQ / 128), 256>>>(
        nullptr, w_proj, b_proj, out, DIM, DIM);
}

// round 8
// speedup vs baseline: 13.1348x; 1.2188x over previous
#include <cuda_runtime.h>
#include <cuda_fp16.h>
#include <cstdint>

#define BATCH 8
#define NSEQ 1024
#define DIM 768
#define NH 16
#define HD 48
#define SCALE 0.14433756729740643f  /* 48^-0.5 */
#define SP 1032                      /* padded fp32 smem row stride for mix kernel */

// ---------------- scratch (static __device__, allocation-guard safe) ----------
__device__ __align__(256) __half g_xh[BATCH * NSEQ * DIM];          // x in fp16
__device__ __align__(256) __half g_wqkvh[3 * DIM * DIM];            // w_qkv in fp16
__device__ __align__(256) __half g_wprojh[DIM * DIM];               // w_proj in fp16
__device__ __align__(256) __half g_q[BATCH * NH * NSEQ * HD];       // [b][h][n][d] (pre-scaled)
__device__ __align__(256) __half g_k[BATCH * NH * NSEQ * HD];       // [b][h][n][d]
__device__ __align__(256) __half g_v[BATCH * NH * HD * NSEQ];       // [b][h][d][n]  TRANSPOSED
__device__ __align__(256) __half g_S[(size_t)BATCH * NH * NSEQ * NSEQ];  // logits -> probs
__device__ __align__(256) __half g_O[BATCH * NSEQ * DIM];           // attn out pre-proj (fp16)

// ---------------- helpers -----------------------------------------------------
__device__ __forceinline__ uint32_t f2tf(float x) {
    uint32_t r;
    asm("cvt.rna.tf32.f32 %0, %1;" : "=r"(r) : "f"(x));
    return r;
}
__device__ __forceinline__ void mma8(float* c, const uint32_t* a, const uint32_t* b) {
    asm volatile(
        "mma.sync.aligned.m16n8k8.row.col.f32.tf32.tf32.f32 "
        "{%0,%1,%2,%3},{%4,%5,%6,%7},{%8,%9},{%0,%1,%2,%3};"
        : "+f"(c[0]), "+f"(c[1]), "+f"(c[2]), "+f"(c[3])
        : "r"(a[0]), "r"(a[1]), "r"(a[2]), "r"(a[3]), "r"(b[0]), "r"(b[1]));
}
__device__ __forceinline__ void mma16h(float* c, const uint32_t* a, const uint32_t* b) {
    asm volatile(
        "mma.sync.aligned.m16n8k16.row.col.f32.f16.f16.f32 "
        "{%0,%1,%2,%3},{%4,%5,%6,%7},{%8,%9},{%0,%1,%2,%3};"
        : "+f"(c[0]), "+f"(c[1]), "+f"(c[2]), "+f"(c[3])
        : "r"(a[0]), "r"(a[1]), "r"(a[2]), "r"(a[3]), "r"(b[0]), "r"(b[1]));
}

#define CP16(dst_u32, src_ptr) \
    asm volatile("cp.async.cg.shared.global [%0], [%1], 16;" :: "r"(dst_u32), "l"(src_ptr))
#define CP_COMMIT() asm volatile("cp.async.commit_group;" ::)
#define CP_WAIT0()  asm volatile("cp.async.wait_group 0;" ::)

// ---------------- K0: fp32 -> fp16 conversion (grid-stride, float4 wide) ------
__global__ __launch_bounds__(256) void f2h_kernel(
    const float* __restrict__ in, __half* __restrict__ out, int n4) {
    for (int i = blockIdx.x * 256 + threadIdx.x; i < n4; i += gridDim.x * 256) {
        float4 v = ((const float4*)in)[i];
        __half2 a = __floats2half2_rn(v.x, v.y);
        __half2 b = __floats2half2_rn(v.z, v.w);
        ((__half2*)out)[2 * i] = a;
        ((__half2*)out)[2 * i + 1] = b;
    }
}

// ---------------- mm_fp16: qkv (MODE 0) & proj (MODE 1), cp.async dbuf --------
// Block 128x128, K-tile 32, 8 warps (2Mx4N), warp tile 64x32. fp16 in, fp32 acc.
template <int MODE>
__global__ __launch_bounds__(256) void mm_fp16(
    const __half* __restrict__ A, const __half* __restrict__ W,
    const float* __restrict__ bias, float* __restrict__ C, int K, int Nc) {
    __shared__ __half As[2][128][40];   // fragment word 20g+t: all-distinct mod 32
    __shared__ __half Ws[2][128][40];

    const int tid = threadIdx.x;
    const int m0 = blockIdx.y * 128;
    const int n0 = blockIdx.x * 128;

    const int warp = tid >> 5, lane = tid & 31;
    const int wm = warp >> 2, wn = warp & 3;
    const int g = lane >> 2, t = lane & 3;

    const int lr = tid >> 2;            // 0..63 (also row lr+64)
    const int lc = (tid & 3) * 8;       // 0,8,16,24 halfs

    const uint32_t sa = (uint32_t)__cvta_generic_to_shared(&As[0][0][0]);
    const uint32_t sw = (uint32_t)__cvta_generic_to_shared(&Ws[0][0][0]);
    const uint32_t d0 = (uint32_t)(lr * 40 + lc) * 2;
    const uint32_t d1 = (uint32_t)((lr + 64) * 40 + lc) * 2;
    const uint32_t bufoff = 128 * 40 * 2;

#define MM_CP(buf, kt)                                                         \
    do {                                                                       \
        CP16(sa + (buf) * bufoff + d0, A + (size_t)(m0 + lr) * K + (kt) + lc);      \
        CP16(sa + (buf) * bufoff + d1, A + (size_t)(m0 + lr + 64) * K + (kt) + lc); \
        CP16(sw + (buf) * bufoff + d0, W + (size_t)(n0 + lr) * K + (kt) + lc);      \
        CP16(sw + (buf) * bufoff + d1, W + (size_t)(n0 + lr + 64) * K + (kt) + lc); \
        CP_COMMIT();                                                           \
    } while (0)

    float acc[4][4][4];
#pragma unroll
    for (int i = 0; i < 4; i++)
#pragma unroll
        for (int j = 0; j < 4; j++)
#pragma unroll
            for (int e = 0; e < 4; e++) acc[i][j][e] = 0.f;

    MM_CP(0, 0);
    CP_WAIT0();
    __syncthreads();

    int buf = 0;
    for (int kt = 32;; kt += 32) {
        const bool more = kt < K;
        if (more) MM_CP(buf ^ 1, kt);
#pragma unroll
        for (int ks = 0; ks < 2; ks++) {
            const int kb = ks * 16 + 2 * t;
            uint32_t af[4][4], bf[4][2];
#pragma unroll
            for (int mt = 0; mt < 4; mt++) {
                const int r = wm * 64 + mt * 16 + g;
                af[mt][0] = *(const uint32_t*)&As[buf][r][kb];
                af[mt][1] = *(const uint32_t*)&As[buf][r + 8][kb];
                af[mt][2] = *(const uint32_t*)&As[buf][r][kb + 8];
                af[mt][3] = *(const uint32_t*)&As[buf][r + 8][kb + 8];
            }
#pragma unroll
            for (int nt = 0; nt < 4; nt++) {
                const int n = wn * 32 + nt * 8 + g;
                bf[nt][0] = *(const uint32_t*)&Ws[buf][n][kb];
                bf[nt][1] = *(const uint32_t*)&Ws[buf][n][kb + 8];
            }
#pragma unroll
            for (int mt = 0; mt < 4; mt++)
#pragma unroll
                for (int nt = 0; nt < 4; nt++) mma16h(acc[mt][nt], af[mt], bf[nt]);
        }
        if (!more) break;
        CP_WAIT0();
        __syncthreads();
        buf ^= 1;
    }

#pragma unroll
    for (int mt = 0; mt < 4; mt++) {
#pragma unroll
        for (int nt = 0; nt < 4; nt++) {
#pragma unroll
            for (int half = 0; half < 2; half++) {
                const int m = m0 + wm * 64 + mt * 16 + g + half * 8;
                const int c = n0 + wn * 32 + nt * 8 + 2 * t;
                const float v0 = acc[mt][nt][half * 2 + 0];
                const float v1 = acc[mt][nt][half * 2 + 1];
                if (MODE == 0) {
#pragma unroll
                    for (int e = 0; e < 2; e++) {
                        const int cc = c + e;
                        float v = (e ? v1 : v0) + bias[cc];
                        const int b = m >> 10, n = m & 1023;
                        const int tt = cc / DIM;
                        const int rr = cc - tt * DIM;
                        const int h = rr / HD, d = rr - h * HD;
                        const int bh = b * NH + h;
                        if (tt == 0)
                            g_q[((size_t)bh * NSEQ + n) * HD + d] = __float2half(v * SCALE);
                        else if (tt == 1)
                            g_k[((size_t)bh * NSEQ + n) * HD + d] = __float2half(v);
                        else
                            g_v[((size_t)bh * HD + d) * NSEQ + n] = __float2half(v);
                    }
                } else {
                    float2 o = make_float2(v0 + bias[c], v1 + bias[c + 1]);
                    *(float2*)(C + (size_t)m * Nc + c) = o;
                }
            }
        }
    }
#undef MM_CP
}

// ---------------- K2: S = q @ k^T per (b,h), fp16 mma, K=48 single-shot -------
__global__ __launch_bounds__(256) void qk_fp16() {
    __shared__ __half Qs[128][56];
    __shared__ __half Ks[128][56];

    const int tid = threadIdx.x;
    const int bh = blockIdx.z;
    const int q0 = blockIdx.y * 128;
    const int k0 = blockIdx.x * 128;

    const __half* Qg = g_q + (size_t)bh * NSEQ * HD;
    const __half* Kg = g_k + (size_t)bh * NSEQ * HD;

    const uint32_t sq = (uint32_t)__cvta_generic_to_shared(&Qs[0][0]);
    const uint32_t sk = (uint32_t)__cvta_generic_to_shared(&Ks[0][0]);

#pragma unroll
    for (int j = 0; j < 3; j++) {
        const int i = tid + 256 * j;
        const int r = i / 6, c = (i % 6) * 8;
        CP16(sq + (uint32_t)(r * 56 + c) * 2, Qg + (size_t)(q0 + r) * HD + c);
        CP16(sk + (uint32_t)(r * 56 + c) * 2, Kg + (size_t)(k0 + r) * HD + c);
    }
    CP_COMMIT();
    CP_WAIT0();
    __syncthreads();

    const int warp = tid >> 5, lane = tid & 31;
    const int wm = warp >> 2, wn = warp & 3;
    const int g = lane >> 2, t = lane & 3;

    float acc[4][4][4];
#pragma unroll
    for (int i = 0; i < 4; i++)
#pragma unroll
        for (int j = 0; j < 4; j++)
#pragma unroll
            for (int e = 0; e < 4; e++) acc[i][j][e] = 0.f;

#pragma unroll
    for (int ks = 0; ks < 3; ks++) {
        const int kb = ks * 16 + 2 * t;
        uint32_t af[4][4], bf[4][2];
#pragma unroll
        for (int mt = 0; mt < 4; mt++) {
            const int r = wm * 64 + mt * 16 + g;
            af[mt][0] = *(const uint32_t*)&Qs[r][kb];
            af[mt][1] = *(const uint32_t*)&Qs[r + 8][kb];
            af[mt][2] = *(const uint32_t*)&Qs[r][kb + 8];
            af[mt][3] = *(const uint32_t*)&Qs[r + 8][kb + 8];
        }
#pragma unroll
        for (int nt = 0; nt < 4; nt++) {
            const int n = wn * 32 + nt * 8 + g;
            bf[nt][0] = *(const uint32_t*)&Ks[n][kb];
            bf[nt][1] = *(const uint32_t*)&Ks[n][kb + 8];
        }
#pragma unroll
        for (int mt = 0; mt < 4; mt++)
#pragma unroll
            for (int nt = 0; nt < 4; nt++) mma16h(acc[mt][nt], af[mt], bf[nt]);
    }

    __half* Sg = g_S + (size_t)bh * NSEQ * NSEQ;
#pragma unroll
    for (int mt = 0; mt < 4; mt++)
#pragma unroll
        for (int nt = 0; nt < 4; nt++)
#pragma unroll
            for (int half = 0; half < 2; half++) {
                const int m = q0 + wm * 64 + mt * 16 + g + half * 8;
                const int c = k0 + wn * 32 + nt * 8 + 2 * t;
                *(__half2*)(Sg + (size_t)m * NSEQ + c) =
                    __floats2half2_rn(acc[mt][nt][half * 2], acc[mt][nt][half * 2 + 1]);
            }
}

// ---------------- K3: mix1 -> softmax -> mix2; fp16 I/O, mma mixes ------------
__global__ __launch_bounds__(256) void mix_softmax_kernel(
    const float* __restrict__ wl, const float* __restrict__ bl,
    const float* __restrict__ ww, const float* __restrict__ bw) {
    extern __shared__ float s[];  // [16][SP]

    const int tid = threadIdx.x;
    const int lane = tid & 31, warp = tid >> 5;
    const int ar = lane >> 2;
    const int ac = lane & 3;
    const int bq = blockIdx.x;
    const int b = bq >> 10, q = bq & 1023;

    uint32_t la[2][4], wa[2][4];
#pragma unroll
    for (int kh = 0; kh < 2; kh++) {
        la[kh][0] = f2tf(wl[ar * NH + kh * 8 + ac]);
        la[kh][1] = f2tf(wl[(ar + 8) * NH + kh * 8 + ac]);
        la[kh][2] = f2tf(wl[ar * NH + kh * 8 + ac + 4]);
        la[kh][3] = f2tf(wl[(ar + 8) * NH + kh * 8 + ac + 4]);
        wa[kh][0] = f2tf(ww[ar * NH + kh * 8 + ac]);
        wa[kh][1] = f2tf(ww[(ar + 8) * NH + kh * 8 + ac]);
        wa[kh][2] = f2tf(ww[ar * NH + kh * 8 + ac + 4]);
        wa[kh][3] = f2tf(ww[(ar + 8) * NH + kh * 8 + ac + 4]);
    }
    const float bl0 = bl[ar], bl1 = bl[ar + 8];
    const float bw0 = bw[ar], bw1 = bw[ar + 8];

    const size_t rowbase = (size_t)(b * NH) * NSEQ * NSEQ + (size_t)q * NSEQ;
#pragma unroll
    for (int h = 0; h < NH; h++) {
        const __half2* src = (const __half2*)(g_S + rowbase + (size_t)h * NSEQ * NSEQ);
#pragma unroll
        for (int j = 0; j < 2; j++) {
            const int i = tid + 256 * j;
            const float2 f = __half22float2(src[i]);
            s[h * SP + 2 * i] = f.x;
            s[h * SP + 2 * i + 1] = f.y;
        }
    }
    __syncthreads();

    // mix1 via mma, in place
#pragma unroll 4
    for (int c0 = warp * 128; c0 < warp * 128 + 128; c0 += 8) {
        uint32_t bf0[2], bf1[2];
        bf0[0] = f2tf(s[ac * SP + c0 + ar]);
        bf0[1] = f2tf(s[(ac + 4) * SP + c0 + ar]);
        bf1[0] = f2tf(s[(8 + ac) * SP + c0 + ar]);
        bf1[1] = f2tf(s[(12 + ac) * SP + c0 + ar]);
        float c[4] = {bl0, bl0, bl1, bl1};
        mma8(c, la[0], bf0);
        mma8(c, la[1], bf1);
        __syncwarp();
        *(float2*)(s + ar * SP + c0 + 2 * ac) = make_float2(c[0], c[1]);
        *(float2*)(s + (ar + 8) * SP + c0 + 2 * ac) = make_float2(c[2], c[3]);
        __syncwarp();
    }
    __syncthreads();

    // softmax per head row
    for (int gg = warp; gg < NH; gg += 8) {
        float* row = s + gg * SP;
        float mx = -1e30f;
        for (int k = lane; k < NSEQ; k += 32) mx = fmaxf(mx, row[k]);
#pragma unroll
        for (int off = 16; off > 0; off >>= 1) mx = fmaxf(mx, __shfl_xor_sync(0xffffffffu, mx, off));
        float sum = 0.f;
        for (int k = lane; k < NSEQ; k += 32) {
            float e = __expf(row[k] - mx);
            row[k] = e;
            sum += e;
        }
#pragma unroll
        for (int off = 16; off > 0; off >>= 1) sum += __shfl_xor_sync(0xffffffffu, sum, off);
        const float inv = 1.f / sum;
        for (int k = lane; k < NSEQ; k += 32) row[k] *= inv;
    }
    __syncthreads();

    // mix2 via mma, write fp16 to g_S
#pragma unroll 4
    for (int c0 = warp * 128; c0 < warp * 128 + 128; c0 += 8) {
        uint32_t bf0[2], bf1[2];
        bf0[0] = f2tf(s[ac * SP + c0 + ar]);
        bf0[1] = f2tf(s[(ac + 4) * SP + c0 + ar]);
        bf1[0] = f2tf(s[(8 + ac) * SP + c0 + ar]);
        bf1[1] = f2tf(s[(12 + ac) * SP + c0 + ar]);
        float c[4] = {bw0, bw0, bw1, bw1};
        mma8(c, wa[0], bf0);
        mma8(c, wa[1], bf1);
        *(__half2*)(g_S + rowbase + (size_t)ar * NSEQ * NSEQ + c0 + 2 * ac) =
            __floats2half2_rn(c[0], c[1]);
        *(__half2*)(g_S + rowbase + (size_t)(ar + 8) * NSEQ * NSEQ + c0 + 2 * ac) =
            __floats2half2_rn(c[2], c[3]);
    }
}

// ---------------- K4: O = P @ V per (b,h), fp16 mma + cp.async dbuf -----------
__global__ __launch_bounds__(256) void pv_fp16() {
    __shared__ __half Ps[2][128][40];
    __shared__ __half Vs[2][HD][40];

    const int bh = blockIdx.z;
    const int tid = threadIdx.x;
    const int qbase = blockIdx.x * 128;
    const __half* Pg = g_S + (size_t)bh * NSEQ * NSEQ + (size_t)qbase * NSEQ;
    const __half* Vg = g_v + (size_t)bh * HD * NSEQ;   // [d][n]

    const int warp = tid >> 5, lane = tid & 31;
    const int wm = warp >> 1, wn = warp & 1;
    const int g = lane >> 2, t = lane & 3;

    const uint32_t psa = (uint32_t)__cvta_generic_to_shared(&Ps[0][0][0]);
    const uint32_t vsa = (uint32_t)__cvta_generic_to_shared(&Vs[0][0][0]);
    const uint32_t PSZ = 128 * 40 * 2;
    const uint32_t VSZ = HD * 40 * 2;

#define PV_CP(buf, kt)                                                          \
    do {                                                                        \
        _Pragma("unroll")                                                       \
        for (int j = 0; j < 2; j++) {                                           \
            const int i = tid + 256 * j;                                        \
            const int r = i >> 2, c = (i & 3) * 8;                              \
            CP16(psa + (buf) * PSZ + (uint32_t)(r * 40 + c) * 2,                \
                 Pg + (size_t)r * NSEQ + (kt) + c);                             \
        }                                                                       \
        if (tid < 192) {                                                        \
            const int d = tid >> 2, c = (tid & 3) * 8;                          \
            CP16(vsa + (buf) * VSZ + (uint32_t)(d * 40 + c) * 2,                \
                 Vg + (size_t)d * NSEQ + (kt) + c);                             \
        }                                                                       \
        CP_COMMIT();                                                            \
    } while (0)

    float acc[2][3][4];
#pragma unroll
    for (int i = 0; i < 2; i++)
#pragma unroll
        for (int j = 0; j < 3; j++)
#pragma unroll
            for (int e = 0; e < 4; e++) acc[i][j][e] = 0.f;

    PV_CP(0, 0);
    CP_WAIT0();
    __syncthreads();

    int buf = 0;
    for (int kt = 32;; kt += 32) {
        const bool more = kt < NSEQ;
        if (more) PV_CP(buf ^ 1, kt);
#pragma unroll
        for (int ks = 0; ks < 2; ks++) {
            const int kb = ks * 16 + 2 * t;
            uint32_t af[2][4], bf[3][2];
#pragma unroll
            for (int mt = 0; mt < 2; mt++) {
                const int r = wm * 32 + mt * 16 + g;
                af[mt][0] = *(const uint32_t*)&Ps[buf][r][kb];
                af[mt][1] = *(const uint32_t*)&Ps[buf][r + 8][kb];
                af[mt][2] = *(const uint32_t*)&Ps[buf][r][kb + 8];
                af[mt][3] = *(const uint32_t*)&Ps[buf][r + 8][kb + 8];
            }
#pragma unroll
            for (int nt = 0; nt < 3; nt++) {
                const int n = wn * 24 + nt * 8 + g;
                bf[nt][0] = *(const uint32_t*)&Vs[buf][n][kb];
                bf[nt][1] = *(const uint32_t*)&Vs[buf][n][kb + 8];
            }
#pragma unroll
            for (int mt = 0; mt < 2; mt++)
#pragma unroll
                for (int nt = 0; nt < 3; nt++) mma16h(acc[mt][nt], af[mt], bf[nt]);
        }
        if (!more) break;
        CP_WAIT0();
        __syncthreads();
        buf ^= 1;
    }

    const int b = bh >> 4, h = bh & 15;
#pragma unroll
    for (int mt = 0; mt < 2; mt++)
#pragma unroll
        for (int nt = 0; nt < 3; nt++)
#pragma unroll
            for (int half = 0; half < 2; half++) {
                const int q = qbase + wm * 32 + mt * 16 + g + half * 8;
                const int d = wn * 24 + nt * 8 + 2 * t;
                *(__half2*)(g_O + (size_t)(b * NSEQ + q) * DIM + h * HD + d) =
                    __floats2half2_rn(acc[mt][nt][half * 2], acc[mt][nt][half * 2 + 1]);
            }
#undef PV_CP
}

// ---------------- launch ------------------------------------------------------
extern "C" void kernel_launch(void* const* d_in, const int* in_sizes, int n_in,
                              void* d_out, int out_size) {
    const float* x      = (const float*)d_in[0];
    const float* w_qkv  = (const float*)d_in[1];
    const float* b_qkv  = (const float*)d_in[2];
    const float* w_l    = (const float*)d_in[3];
    const float* b_l    = (const float*)d_in[4];
    const float* w_w    = (const float*)d_in[5];
    const float* b_w    = (const float*)d_in[6];
    const float* w_proj = (const float*)d_in[7];
    const float* b_proj = (const float*)d_in[8];
    float* out = (float*)d_out;

    cudaFuncSetAttribute(mix_softmax_kernel,
                         cudaFuncAttributeMaxDynamicSharedMemorySize, NH * SP * 4);

    __half* xh;  cudaGetSymbolAddress((void**)&xh, g_xh);
    __half* wqh; cudaGetSymbolAddress((void**)&wqh, g_wqkvh);
    __half* wph; cudaGetSymbolAddress((void**)&wph, g_wprojh);
    __half* Oh;  cudaGetSymbolAddress((void**)&Oh, g_O);

    // K0: fp32 -> fp16 conversions
    f2h_kernel<<<592, 256>>>(x, xh, BATCH * NSEQ * DIM / 4);
    f2h_kernel<<<296, 256>>>(w_qkv, wqh, 3 * DIM * DIM / 4);
    f2h_kernel<<<148, 256>>>(w_proj, wph, DIM * DIM / 4);

    // K1: QKV projection  [M=8192, N=2304, K=768], fp16 -> fp16 q/k/v (v transposed)
    mm_fp16<0><<<dim3(3 * DIM / 128, BATCH * NSEQ / 128), 256>>>(
        xh, wqh, b_qkv, nullptr, DIM, 3 * DIM);
    // K2: logits S = q @ k^T per (b,h), fp16
    qk_fp16<<<dim3(NSEQ / 128, NSEQ / 128, BATCH * NH), 256>>>();
    // K3: mix1 + softmax + mix2 (in place, fp16 I/O)
    mix_softmax_kernel<<<BATCH * NSEQ, 256, NH * SP * 4>>>(w_l, b_l, w_w, b_w);
    // K4: P @ V -> g_O (fp16)
    pv_fp16<<<dim3(NSEQ / 128, 1, BATCH * NH), 256>>>();
    // K5: output projection  [M=8192, N=768, K=768], fp16 in, fp32 out
    mm_fp16<1><<<dim3(DIM / 128, BATCH * NSEQ / 128), 256>>>(
        Oh, wph, b_proj, out, DIM, DIM);
}

// round 9
// speedup vs baseline: 13.4408x; 1.0233x over previous
#include <cuda_runtime.h>
#include <cuda_fp16.h>
#include <cstdint>

#define BATCH 8
#define NSEQ 1024
#define DIM 768
#define NH 16
#define HD 48
#define SCALE 0.14433756729740643f  /* 48^-0.5 */
#define SP 1032                      /* padded fp32 smem row stride for mix kernel */

// ---------------- scratch (static __device__, allocation-guard safe) ----------
__device__ __align__(256) __half g_xh[BATCH * NSEQ * DIM];
__device__ __align__(256) __half g_wqkvh[3 * DIM * DIM];
__device__ __align__(256) __half g_wprojh[DIM * DIM];
__device__ __align__(256) __half g_q[BATCH * NH * NSEQ * HD];       // [b][h][n][d] (pre-scaled)
__device__ __align__(256) __half g_k[BATCH * NH * NSEQ * HD];       // [b][h][n][d]
__device__ __align__(256) __half g_v[BATCH * NH * HD * NSEQ];       // [b][h][d][n]  TRANSPOSED
__device__ __align__(256) __half g_S[(size_t)BATCH * NH * NSEQ * NSEQ];
__device__ __align__(256) __half g_O[BATCH * NSEQ * DIM];           // attn out pre-proj (fp16)

// ---------------- helpers -----------------------------------------------------
__device__ __forceinline__ uint32_t f2tf(float x) {
    uint32_t r;
    asm("cvt.rna.tf32.f32 %0, %1;" : "=r"(r) : "f"(x));
    return r;
}
__device__ __forceinline__ void mma8(float* c, const uint32_t* a, const uint32_t* b) {
    asm volatile(
        "mma.sync.aligned.m16n8k8.row.col.f32.tf32.tf32.f32 "
        "{%0,%1,%2,%3},{%4,%5,%6,%7},{%8,%9},{%0,%1,%2,%3};"
        : "+f"(c[0]), "+f"(c[1]), "+f"(c[2]), "+f"(c[3])
        : "r"(a[0]), "r"(a[1]), "r"(a[2]), "r"(a[3]), "r"(b[0]), "r"(b[1]));
}
__device__ __forceinline__ void mma16h(float* c, const uint32_t* a, const uint32_t* b) {
    asm volatile(
        "mma.sync.aligned.m16n8k16.row.col.f32.f16.f16.f32 "
        "{%0,%1,%2,%3},{%4,%5,%6,%7},{%8,%9},{%0,%1,%2,%3};"
        : "+f"(c[0]), "+f"(c[1]), "+f"(c[2]), "+f"(c[3])
        : "r"(a[0]), "r"(a[1]), "r"(a[2]), "r"(a[3]), "r"(b[0]), "r"(b[1]));
}
__device__ __forceinline__ void ldsm4(uint32_t& r0, uint32_t& r1, uint32_t& r2, uint32_t& r3,
                                      uint32_t addr) {
    asm volatile("ldmatrix.sync.aligned.m8n8.x4.shared.b16 {%0,%1,%2,%3}, [%4];"
        : "=r"(r0), "=r"(r1), "=r"(r2), "=r"(r3) : "r"(addr));
}
__device__ __forceinline__ void ldsm2(uint32_t& r0, uint32_t& r1, uint32_t addr) {
    asm volatile("ldmatrix.sync.aligned.m8n8.x2.shared.b16 {%0,%1}, [%2];"
        : "=r"(r0), "=r"(r1) : "r"(addr));
}

#define CP16(dst_u32, src_ptr) \
    asm volatile("cp.async.cg.shared.global [%0], [%1], 16;" :: "r"(dst_u32), "l"(src_ptr))
#define CP_COMMIT() asm volatile("cp.async.commit_group;" ::)
#define CP_WAIT0()  asm volatile("cp.async.wait_group 0;" ::)

// ---------------- K0: fp32 -> fp16 conversion ---------------------------------
__global__ __launch_bounds__(256) void f2h_kernel(
    const float* __restrict__ in, __half* __restrict__ out, int n4) {
    for (int i = blockIdx.x * 256 + threadIdx.x; i < n4; i += gridDim.x * 256) {
        float4 v = ((const float4*)in)[i];
        ((__half2*)out)[2 * i]     = __floats2half2_rn(v.x, v.y);
        ((__half2*)out)[2 * i + 1] = __floats2half2_rn(v.z, v.w);
    }
}

// ---------------- mm_fp16: qkv (MODE 0) & proj (MODE 1), ldmatrix + cp.async --
template <int MODE>
__global__ __launch_bounds__(256) void mm_fp16(
    const __half* __restrict__ A, const __half* __restrict__ W,
    const float* __restrict__ bias, float* __restrict__ C, int K, int Nc) {
    __shared__ __half As[2][128][40];
    __shared__ __half Ws[2][128][40];

    const int tid = threadIdx.x;
    const int m0 = blockIdx.y * 128;
    const int n0 = blockIdx.x * 128;

    const int warp = tid >> 5, lane = tid & 31;
    const int wm = warp >> 2, wn = warp & 3;
    const int g = lane >> 2, t = lane & 3;

    const int lr = tid >> 2;
    const int lc = (tid & 3) * 8;

    const uint32_t sa = (uint32_t)__cvta_generic_to_shared(&As[0][0][0]);
    const uint32_t sw = (uint32_t)__cvta_generic_to_shared(&Ws[0][0][0]);
    const uint32_t d0 = (uint32_t)(lr * 40 + lc) * 2;
    const uint32_t d1 = (uint32_t)((lr + 64) * 40 + lc) * 2;
    const uint32_t bufoff = 128 * 40 * 2;

    // ldmatrix per-lane offsets (bytes within tile)
    const uint32_t a_off = (uint32_t)((lane & 15) * 40 + (lane >> 4) * 8) * 2;
    const uint32_t b_off = (uint32_t)((((lane >> 4) << 3) + (lane & 7)) * 40 +
                                      (((lane >> 3) & 1) << 3)) * 2;

#define MM_CP(buf, kt)                                                         \
    do {                                                                       \
        CP16(sa + (buf) * bufoff + d0, A + (size_t)(m0 + lr) * K + (kt) + lc);      \
        CP16(sa + (buf) * bufoff + d1, A + (size_t)(m0 + lr + 64) * K + (kt) + lc); \
        CP16(sw + (buf) * bufoff + d0, W + (size_t)(n0 + lr) * K + (kt) + lc);      \
        CP16(sw + (buf) * bufoff + d1, W + (size_t)(n0 + lr + 64) * K + (kt) + lc); \
        CP_COMMIT();                                                           \
    } while (0)

    float acc[4][4][4];
#pragma unroll
    for (int i = 0; i < 4; i++)
#pragma unroll
        for (int j = 0; j < 4; j++)
#pragma unroll
            for (int e = 0; e < 4; e++) acc[i][j][e] = 0.f;

    MM_CP(0, 0);
    CP_WAIT0();
    __syncthreads();

    int buf = 0;
    for (int kt = 32;; kt += 32) {
        const bool more = kt < K;
        if (more) MM_CP(buf ^ 1, kt);
#pragma unroll
        for (int ks = 0; ks < 2; ks++) {
            const uint32_t kb = (uint32_t)(ks * 16) * 2;
            uint32_t af[4][4], bf[4][2];
#pragma unroll
            for (int mt = 0; mt < 4; mt++)
                ldsm4(af[mt][0], af[mt][1], af[mt][2], af[mt][3],
                      sa + buf * bufoff + (uint32_t)((wm * 64 + mt * 16) * 40) * 2 + kb + a_off);
#pragma unroll
            for (int ntp = 0; ntp < 2; ntp++)
                ldsm4(bf[2 * ntp][0], bf[2 * ntp][1], bf[2 * ntp + 1][0], bf[2 * ntp + 1][1],
                      sw + buf * bufoff + (uint32_t)((wn * 32 + ntp * 16) * 40) * 2 + kb + b_off);
#pragma unroll
            for (int mt = 0; mt < 4; mt++)
#pragma unroll
                for (int nt = 0; nt < 4; nt++) mma16h(acc[mt][nt], af[mt], bf[nt]);
        }
        if (!more) break;
        CP_WAIT0();
        __syncthreads();
        buf ^= 1;
    }

#pragma unroll
    for (int mt = 0; mt < 4; mt++) {
#pragma unroll
        for (int nt = 0; nt < 4; nt++) {
#pragma unroll
            for (int half = 0; half < 2; half++) {
                const int m = m0 + wm * 64 + mt * 16 + g + half * 8;
                const int c = n0 + wn * 32 + nt * 8 + 2 * t;   // always even
                const float v0 = acc[mt][nt][half * 2 + 0];
                const float v1 = acc[mt][nt][half * 2 + 1];
                if (MODE == 0) {
                    const float w0 = v0 + bias[c], w1 = v1 + bias[c + 1];
                    const int b = m >> 10, n = m & 1023;
                    const int tt = c / DIM;
                    const int rr = c - tt * DIM;
                    const int h = rr / HD, d = rr - h * HD;    // d even, d+1 same head
                    const int bh = b * NH + h;
                    if (tt == 0)
                        *(__half2*)&g_q[((size_t)bh * NSEQ + n) * HD + d] =
                            __floats2half2_rn(w0 * SCALE, w1 * SCALE);
                    else if (tt == 1)
                        *(__half2*)&g_k[((size_t)bh * NSEQ + n) * HD + d] =
                            __floats2half2_rn(w0, w1);
                    else {
                        g_v[((size_t)bh * HD + d) * NSEQ + n] = __float2half(w0);
                        g_v[((size_t)bh * HD + d + 1) * NSEQ + n] = __float2half(w1);
                    }
                } else {
                    float2 o = make_float2(v0 + bias[c], v1 + bias[c + 1]);
                    *(float2*)(C + (size_t)m * Nc + c) = o;
                }
            }
        }
    }
#undef MM_CP
}

// ---------------- K2: S = q @ k^T per (b,h), fp16 mma + ldmatrix --------------
__global__ __launch_bounds__(256) void qk_fp16() {
    __shared__ __half Qs[128][56];
    __shared__ __half Ks[128][56];

    const int tid = threadIdx.x;
    const int bh = blockIdx.z;
    const int q0 = blockIdx.y * 128;
    const int k0 = blockIdx.x * 128;

    const __half* Qg = g_q + (size_t)bh * NSEQ * HD;
    const __half* Kg = g_k + (size_t)bh * NSEQ * HD;

    const uint32_t sq = (uint32_t)__cvta_generic_to_shared(&Qs[0][0]);
    const uint32_t sk = (uint32_t)__cvta_generic_to_shared(&Ks[0][0]);

#pragma unroll
    for (int j = 0; j < 3; j++) {
        const int i = tid + 256 * j;
        const int r = i / 6, c = (i % 6) * 8;
        CP16(sq + (uint32_t)(r * 56 + c) * 2, Qg + (size_t)(q0 + r) * HD + c);
        CP16(sk + (uint32_t)(r * 56 + c) * 2, Kg + (size_t)(k0 + r) * HD + c);
    }
    CP_COMMIT();
    CP_WAIT0();
    __syncthreads();

    const int warp = tid >> 5, lane = tid & 31;
    const int wm = warp >> 2, wn = warp & 3;
    const int g = lane >> 2, t = lane & 3;

    const uint32_t a_off = (uint32_t)((lane & 15) * 56 + (lane >> 4) * 8) * 2;
    const uint32_t b_off = (uint32_t)((((lane >> 4) << 3) + (lane & 7)) * 56 +
                                      (((lane >> 3) & 1) << 3)) * 2;

    float acc[4][4][4];
#pragma unroll
    for (int i = 0; i < 4; i++)
#pragma unroll
        for (int j = 0; j < 4; j++)
#pragma unroll
            for (int e = 0; e < 4; e++) acc[i][j][e] = 0.f;

#pragma unroll
    for (int ks = 0; ks < 3; ks++) {
        const uint32_t kb = (uint32_t)(ks * 16) * 2;
        uint32_t af[4][4], bf[4][2];
#pragma unroll
        for (int mt = 0; mt < 4; mt++)
            ldsm4(af[mt][0], af[mt][1], af[mt][2], af[mt][3],
                  sq + (uint32_t)((wm * 64 + mt * 16) * 56) * 2 + kb + a_off);
#pragma unroll
        for (int ntp = 0; ntp < 2; ntp++)
            ldsm4(bf[2 * ntp][0], bf[2 * ntp][1], bf[2 * ntp + 1][0], bf[2 * ntp + 1][1],
                  sk + (uint32_t)((wn * 32 + ntp * 16) * 56) * 2 + kb + b_off);
#pragma unroll
        for (int mt = 0; mt < 4; mt++)
#pragma unroll
            for (int nt = 0; nt < 4; nt++) mma16h(acc[mt][nt], af[mt], bf[nt]);
    }

    __half* Sg = g_S + (size_t)bh * NSEQ * NSEQ;
#pragma unroll
    for (int mt = 0; mt < 4; mt++)
#pragma unroll
        for (int nt = 0; nt < 4; nt++)
#pragma unroll
            for (int half = 0; half < 2; half++) {
                const int m = q0 + wm * 64 + mt * 16 + g + half * 8;
                const int c = k0 + wn * 32 + nt * 8 + 2 * t;
                *(__half2*)(Sg + (size_t)m * NSEQ + c) =
                    __floats2half2_rn(acc[mt][nt][half * 2], acc[mt][nt][half * 2 + 1]);
            }
}

// ---------------- K3: mix1 -> softmax -> mix2 (unchanged) ---------------------
__global__ __launch_bounds__(256) void mix_softmax_kernel(
    const float* __restrict__ wl, const float* __restrict__ bl,
    const float* __restrict__ ww, const float* __restrict__ bw) {
    extern __shared__ float s[];

    const int tid = threadIdx.x;
    const int lane = tid & 31, warp = tid >> 5;
    const int ar = lane >> 2;
    const int ac = lane & 3;
    const int bq = blockIdx.x;
    const int b = bq >> 10, q = bq & 1023;

    uint32_t la[2][4], wa[2][4];
#pragma unroll
    for (int kh = 0; kh < 2; kh++) {
        la[kh][0] = f2tf(wl[ar * NH + kh * 8 + ac]);
        la[kh][1] = f2tf(wl[(ar + 8) * NH + kh * 8 + ac]);
        la[kh][2] = f2tf(wl[ar * NH + kh * 8 + ac + 4]);
        la[kh][3] = f2tf(wl[(ar + 8) * NH + kh * 8 + ac + 4]);
        wa[kh][0] = f2tf(ww[ar * NH + kh * 8 + ac]);
        wa[kh][1] = f2tf(ww[(ar + 8) * NH + kh * 8 + ac]);
        wa[kh][2] = f2tf(ww[ar * NH + kh * 8 + ac + 4]);
        wa[kh][3] = f2tf(ww[(ar + 8) * NH + kh * 8 + ac + 4]);
    }
    const float bl0 = bl[ar], bl1 = bl[ar + 8];
    const float bw0 = bw[ar], bw1 = bw[ar + 8];

    const size_t rowbase = (size_t)(b * NH) * NSEQ * NSEQ + (size_t)q * NSEQ;
#pragma unroll
    for (int h = 0; h < NH; h++) {
        const __half2* src = (const __half2*)(g_S + rowbase + (size_t)h * NSEQ * NSEQ);
#pragma unroll
        for (int j = 0; j < 2; j++) {
            const int i = tid + 256 * j;
            const float2 f = __half22float2(src[i]);
            s[h * SP + 2 * i] = f.x;
            s[h * SP + 2 * i + 1] = f.y;
        }
    }
    __syncthreads();

#pragma unroll 4
    for (int c0 = warp * 128; c0 < warp * 128 + 128; c0 += 8) {
        uint32_t bf0[2], bf1[2];
        bf0[0] = f2tf(s[ac * SP + c0 + ar]);
        bf0[1] = f2tf(s[(ac + 4) * SP + c0 + ar]);
        bf1[0] = f2tf(s[(8 + ac) * SP + c0 + ar]);
        bf1[1] = f2tf(s[(12 + ac) * SP + c0 + ar]);
        float c[4] = {bl0, bl0, bl1, bl1};
        mma8(c, la[0], bf0);
        mma8(c, la[1], bf1);
        __syncwarp();
        *(float2*)(s + ar * SP + c0 + 2 * ac) = make_float2(c[0], c[1]);
        *(float2*)(s + (ar + 8) * SP + c0 + 2 * ac) = make_float2(c[2], c[3]);
        __syncwarp();
    }
    __syncthreads();

    for (int gg = warp; gg < NH; gg += 8) {
        float* row = s + gg * SP;
        float mx = -1e30f;
        for (int k = lane; k < NSEQ; k += 32) mx = fmaxf(mx, row[k]);
#pragma unroll
        for (int off = 16; off > 0; off >>= 1) mx = fmaxf(mx, __shfl_xor_sync(0xffffffffu, mx, off));
        float sum = 0.f;
        for (int k = lane; k < NSEQ; k += 32) {
            float e = __expf(row[k] - mx);
            row[k] = e;
            sum += e;
        }
#pragma unroll
        for (int off = 16; off > 0; off >>= 1) sum += __shfl_xor_sync(0xffffffffu, sum, off);
        const float inv = 1.f / sum;
        for (int k = lane; k < NSEQ; k += 32) row[k] *= inv;
    }
    __syncthreads();

#pragma unroll 4
    for (int c0 = warp * 128; c0 < warp * 128 + 128; c0 += 8) {
        uint32_t bf0[2], bf1[2];
        bf0[0] = f2tf(s[ac * SP + c0 + ar]);
        bf0[1] = f2tf(s[(ac + 4) * SP + c0 + ar]);
        bf1[0] = f2tf(s[(8 + ac) * SP + c0 + ar]);
        bf1[1] = f2tf(s[(12 + ac) * SP + c0 + ar]);
        float c[4] = {bw0, bw0, bw1, bw1};
        mma8(c, wa[0], bf0);
        mma8(c, wa[1], bf1);
        *(__half2*)(g_S + rowbase + (size_t)ar * NSEQ * NSEQ + c0 + 2 * ac) =
            __floats2half2_rn(c[0], c[1]);
        *(__half2*)(g_S + rowbase + (size_t)(ar + 8) * NSEQ * NSEQ + c0 + 2 * ac) =
            __floats2half2_rn(c[2], c[3]);
    }
}

// ---------------- K4: O = P @ V per (b,h), fp16 mma + ldmatrix + cp.async -----
__global__ __launch_bounds__(256) void pv_fp16() {
    __shared__ __half Ps[2][128][40];
    __shared__ __half Vs[2][HD][40];

    const int bh = blockIdx.z;
    const int tid = threadIdx.x;
    const int qbase = blockIdx.x * 128;
    const __half* Pg = g_S + (size_t)bh * NSEQ * NSEQ + (size_t)qbase * NSEQ;
    const __half* Vg = g_v + (size_t)bh * HD * NSEQ;   // [d][n]

    const int warp = tid >> 5, lane = tid & 31;
    const int wm = warp >> 1, wn = warp & 1;
    const int g = lane >> 2, t = lane & 3;

    const uint32_t psa = (uint32_t)__cvta_generic_to_shared(&Ps[0][0][0]);
    const uint32_t vsa = (uint32_t)__cvta_generic_to_shared(&Vs[0][0][0]);
    const uint32_t PSZ = 128 * 40 * 2;
    const uint32_t VSZ = HD * 40 * 2;

    const uint32_t a_off = (uint32_t)((lane & 15) * 40 + (lane >> 4) * 8) * 2;
    const uint32_t b_off = (uint32_t)((((lane >> 4) << 3) + (lane & 7)) * 40 +
                                      (((lane >> 3) & 1) << 3)) * 2;
    const uint32_t b2_off = (uint32_t)((lane & 7) * 40 + (((lane >> 3) & 1) << 3)) * 2;

#define PV_CP(buf, kt)                                                          \
    do {                                                                        \
        _Pragma("unroll")                                                       \
        for (int j = 0; j < 2; j++) {                                           \
            const int i = tid + 256 * j;                                        \
            const int r = i >> 2, c = (i & 3) * 8;                              \
            CP16(psa + (buf) * PSZ + (uint32_t)(r * 40 + c) * 2,                \
                 Pg + (size_t)r * NSEQ + (kt) + c);                             \
        }                                                                       \
        if (tid < 192) {                                                        \
            const int d = tid >> 2, c = (tid & 3) * 8;                          \
            CP16(vsa + (buf) * VSZ + (uint32_t)(d * 40 + c) * 2,                \
                 Vg + (size_t)d * NSEQ + (kt) + c);                             \
        }                                                                       \
        CP_COMMIT();                                                            \
    } while (0)

    float acc[2][3][4];
#pragma unroll
    for (int i = 0; i < 2; i++)
#pragma unroll
        for (int j = 0; j < 3; j++)
#pragma unroll
            for (int e = 0; e < 4; e++) acc[i][j][e] = 0.f;

    PV_CP(0, 0);
    CP_WAIT0();
    __syncthreads();

    int buf = 0;
    for (int kt = 32;; kt += 32) {
        const bool more = kt < NSEQ;
        if (more) PV_CP(buf ^ 1, kt);
#pragma unroll
        for (int ks = 0; ks < 2; ks++) {
            const uint32_t kb = (uint32_t)(ks * 16) * 2;
            uint32_t af[2][4], bf[3][2];
#pragma unroll
            for (int mt = 0; mt < 2; mt++)
                ldsm4(af[mt][0], af[mt][1], af[mt][2], af[mt][3],
                      psa + buf * PSZ + (uint32_t)((wm * 32 + mt * 16) * 40) * 2 + kb + a_off);
            ldsm4(bf[0][0], bf[0][1], bf[1][0], bf[1][1],
                  vsa + buf * VSZ + (uint32_t)((wn * 24) * 40) * 2 + kb + b_off);
            ldsm2(bf[2][0], bf[2][1],
                  vsa + buf * VSZ + (uint32_t)((wn * 24 + 16) * 40) * 2 + kb + b2_off);
#pragma unroll
            for (int mt = 0; mt < 2; mt++)
#pragma unroll
                for (int nt = 0; nt < 3; nt++) mma16h(acc[mt][nt], af[mt], bf[nt]);
        }
        if (!more) break;
        CP_WAIT0();
        __syncthreads();
        buf ^= 1;
    }

    const int b = bh >> 4, h = bh & 15;
#pragma unroll
    for (int mt = 0; mt < 2; mt++)
#pragma unroll
        for (int nt = 0; nt < 3; nt++)
#pragma unroll
            for (int half = 0; half < 2; half++) {
                const int q = qbase + wm * 32 + mt * 16 + g + half * 8;
                const int d = wn * 24 + nt * 8 + 2 * t;
                *(__half2*)(g_O + (size_t)(b * NSEQ + q) * DIM + h * HD + d) =
                    __floats2half2_rn(acc[mt][nt][half * 2], acc[mt][nt][half * 2 + 1]);
            }
#undef PV_CP
}

// ---------------- launch ------------------------------------------------------
extern "C" void kernel_launch(void* const* d_in, const int* in_sizes, int n_in,
                              void* d_out, int out_size) {
    const float* x      = (const float*)d_in[0];
    const float* w_qkv  = (const float*)d_in[1];
    const float* b_qkv  = (const float*)d_in[2];
    const float* w_l    = (const float*)d_in[3];
    const float* b_l    = (const float*)d_in[4];
    const float* w_w    = (const float*)d_in[5];
    const float* b_w    = (const float*)d_in[6];
    const float* w_proj = (const float*)d_in[7];
    const float* b_proj = (const float*)d_in[8];
    float* out = (float*)d_out;

    cudaFuncSetAttribute(mix_softmax_kernel,
                         cudaFuncAttributeMaxDynamicSharedMemorySize, NH * SP * 4);

    __half* xh;  cudaGetSymbolAddress((void**)&xh, g_xh);
    __half* wqh; cudaGetSymbolAddress((void**)&wqh, g_wqkvh);
    __half* wph; cudaGetSymbolAddress((void**)&wph, g_wprojh);
    __half* Oh;  cudaGetSymbolAddress((void**)&Oh, g_O);

    // K0: fp32 -> fp16 conversions
    f2h_kernel<<<592, 256>>>(x, xh, BATCH * NSEQ * DIM / 4);
    f2h_kernel<<<296, 256>>>(w_qkv, wqh, 3 * DIM * DIM / 4);
    f2h_kernel<<<148, 256>>>(w_proj, wph, DIM * DIM / 4);

    // K1: QKV projection  [M=8192, N=2304, K=768]
    mm_fp16<0><<<dim3(3 * DIM / 128, BATCH * NSEQ / 128), 256>>>(
        xh, wqh, b_qkv, nullptr, DIM, 3 * DIM);
    // K2: logits S = q @ k^T per (b,h)
    qk_fp16<<<dim3(NSEQ / 128, NSEQ / 128, BATCH * NH), 256>>>();
    // K3: mix1 + softmax + mix2 (in place)
    mix_softmax_kernel<<<BATCH * NSEQ, 256, NH * SP * 4>>>(w_l, b_l, w_w, b_w);
    // K4: P @ V -> g_O (fp16)
    pv_fp16<<<dim3(NSEQ / 128, 1, BATCH * NH), 256>>>();
    // K5: output projection  [M=8192, N=768, K=768]
    mm_fp16<1><<<dim3(DIM / 128, BATCH * NSEQ / 128), 256>>>(
        Oh, wph, b_proj, out, DIM, DIM);
}

// round 10
// speedup vs baseline: 15.5798x; 1.1591x over previous
#include <cuda_runtime.h>
#include <cuda_fp16.h>
#include <cstdint>

#define BATCH 8
#define NSEQ 1024
#define DIM 768
#define NH 16
#define HD 48
#define SCALE 0.14433756729740643f  /* 48^-0.5 */
#define SPH 1032                     /* fp16 smem stride (halfs): 516 words, 516%8==4 */

// ---------------- scratch (static __device__, allocation-guard safe) ----------
__device__ __align__(256) __half g_xh[BATCH * NSEQ * DIM];
__device__ __align__(256) __half g_wqkvh[3 * DIM * DIM];
__device__ __align__(256) __half g_wprojh[DIM * DIM];
__device__ __align__(256) __half g_q[BATCH * NH * NSEQ * HD];       // [b][h][n][d] (pre-scaled)
__device__ __align__(256) __half g_k[BATCH * NH * NSEQ * HD];       // [b][h][n][d]
__device__ __align__(256) __half g_v[BATCH * NH * HD * NSEQ];       // [b][h][d][n]  TRANSPOSED
__device__ __align__(256) __half g_S[(size_t)BATCH * NH * NSEQ * NSEQ];
__device__ __align__(256) __half g_O[BATCH * NSEQ * DIM];           // attn out pre-proj (fp16)

// ---------------- helpers -----------------------------------------------------
__device__ __forceinline__ void mma16h(float* c, const uint32_t* a, const uint32_t* b) {
    asm volatile(
        "mma.sync.aligned.m16n8k16.row.col.f32.f16.f16.f32 "
        "{%0,%1,%2,%3},{%4,%5,%6,%7},{%8,%9},{%0,%1,%2,%3};"
        : "+f"(c[0]), "+f"(c[1]), "+f"(c[2]), "+f"(c[3])
        : "r"(a[0]), "r"(a[1]), "r"(a[2]), "r"(a[3]), "r"(b[0]), "r"(b[1]));
}
__device__ __forceinline__ void ldsm4(uint32_t& r0, uint32_t& r1, uint32_t& r2, uint32_t& r3,
                                      uint32_t addr) {
    asm volatile("ldmatrix.sync.aligned.m8n8.x4.shared.b16 {%0,%1,%2,%3}, [%4];"
        : "=r"(r0), "=r"(r1), "=r"(r2), "=r"(r3) : "r"(addr));
}
__device__ __forceinline__ void ldsm2(uint32_t& r0, uint32_t& r1, uint32_t addr) {
    asm volatile("ldmatrix.sync.aligned.m8n8.x2.shared.b16 {%0,%1}, [%2];"
        : "=r"(r0), "=r"(r1) : "r"(addr));
}
__device__ __forceinline__ void ldsm2t(uint32_t& r0, uint32_t& r1, uint32_t addr) {
    asm volatile("ldmatrix.sync.aligned.m8n8.x2.trans.shared.b16 {%0,%1}, [%2];"
        : "=r"(r0), "=r"(r1) : "r"(addr));
}
__device__ __forceinline__ uint32_t packh2(float x, float y) {
    __half2 h = __floats2half2_rn(x, y);
    return *(uint32_t*)&h;
}

#define CP16(dst_u32, src_ptr) \
    asm volatile("cp.async.cg.shared.global [%0], [%1], 16;" :: "r"(dst_u32), "l"(src_ptr))
#define CP_COMMIT()  asm volatile("cp.async.commit_group;" ::)
#define CP_WAIT(n)   asm volatile("cp.async.wait_group %0;" :: "n"(n))

// ---------------- K0: fp32 -> fp16 conversion ---------------------------------
__global__ __launch_bounds__(256) void f2h_kernel(
    const float* __restrict__ in, __half* __restrict__ out, int n4) {
    for (int i = blockIdx.x * 256 + threadIdx.x; i < n4; i += gridDim.x * 256) {
        float4 v = ((const float4*)in)[i];
        ((__half2*)out)[2 * i]     = __floats2half2_rn(v.x, v.y);
        ((__half2*)out)[2 * i + 1] = __floats2half2_rn(v.z, v.w);
    }
}

// ---------------- mm_fp16: qkv (MODE 0) & proj (MODE 1), 3-stage pipeline -----
template <int MODE>
__global__ __launch_bounds__(256) void mm_fp16(
    const __half* __restrict__ A, const __half* __restrict__ W,
    const float* __restrict__ bias, float* __restrict__ C, int K, int Nc) {
    extern __shared__ __half smem_mm[];   // [3][128][40] A then [3][128][40] W

    const int tid = threadIdx.x;
    const int m0 = blockIdx.y * 128;
    const int n0 = blockIdx.x * 128;

    const int warp = tid >> 5, lane = tid & 31;
    const int wm = warp >> 2, wn = warp & 3;
    const int g = lane >> 2, t = lane & 3;

    const int lr = tid >> 2;
    const int lc = (tid & 3) * 8;

    const uint32_t bufoff = 128 * 40 * 2;
    const uint32_t sa = (uint32_t)__cvta_generic_to_shared(smem_mm);
    const uint32_t sw = sa + 3 * bufoff;
    const uint32_t d0 = (uint32_t)(lr * 40 + lc) * 2;
    const uint32_t d1 = (uint32_t)((lr + 64) * 40 + lc) * 2;

    const uint32_t a_off = (uint32_t)((lane & 15) * 40 + (lane >> 4) * 8) * 2;
    const uint32_t b_off = (uint32_t)((((lane >> 4) << 3) + (lane & 7)) * 40 +
                                      (((lane >> 3) & 1) << 3)) * 2;

#define MM_CP(buf, kt)                                                         \
    do {                                                                       \
        CP16(sa + (buf) * bufoff + d0, A + (size_t)(m0 + lr) * K + (kt) + lc);      \
        CP16(sa + (buf) * bufoff + d1, A + (size_t)(m0 + lr + 64) * K + (kt) + lc); \
        CP16(sw + (buf) * bufoff + d0, W + (size_t)(n0 + lr) * K + (kt) + lc);      \
        CP16(sw + (buf) * bufoff + d1, W + (size_t)(n0 + lr + 64) * K + (kt) + lc); \
        CP_COMMIT();                                                           \
    } while (0)

    float acc[4][4][4];
#pragma unroll
    for (int i = 0; i < 4; i++)
#pragma unroll
        for (int j = 0; j < 4; j++)
#pragma unroll
            for (int e = 0; e < 4; e++) acc[i][j][e] = 0.f;

    const int ntiles = K / 32;            // >= 2 always (K=768)
    MM_CP(0, 0);
    MM_CP(1, 32);
    CP_WAIT(1);
    __syncthreads();

    int buf = 0;
    for (int tt = 0; tt < ntiles; tt++) {
        const int pf = tt + 2;
        if (pf < ntiles) MM_CP(pf % 3, pf * 32);
#pragma unroll
        for (int ks = 0; ks < 2; ks++) {
            const uint32_t kb = (uint32_t)(ks * 16) * 2;
            uint32_t af[4][4], bf[4][2];
#pragma unroll
            for (int mt = 0; mt < 4; mt++)
                ldsm4(af[mt][0], af[mt][1], af[mt][2], af[mt][3],
                      sa + buf * bufoff + (uint32_t)((wm * 64 + mt * 16) * 40) * 2 + kb + a_off);
#pragma unroll
            for (int ntp = 0; ntp < 2; ntp++)
                ldsm4(bf[2 * ntp][0], bf[2 * ntp][1], bf[2 * ntp + 1][0], bf[2 * ntp + 1][1],
                      sw + buf * bufoff + (uint32_t)((wn * 32 + ntp * 16) * 40) * 2 + kb + b_off);
#pragma unroll
            for (int mt = 0; mt < 4; mt++)
#pragma unroll
                for (int nt = 0; nt < 4; nt++) mma16h(acc[mt][nt], af[mt], bf[nt]);
        }
        if (tt + 1 < ntiles) {
            if (pf < ntiles) { CP_WAIT(1); } else { CP_WAIT(0); }
            __syncthreads();
            buf = (buf + 1) % 3;
        }
    }

#pragma unroll
    for (int mt = 0; mt < 4; mt++) {
#pragma unroll
        for (int nt = 0; nt < 4; nt++) {
#pragma unroll
            for (int half = 0; half < 2; half++) {
                const int m = m0 + wm * 64 + mt * 16 + g + half * 8;
                const int c = n0 + wn * 32 + nt * 8 + 2 * t;   // always even
                const float v0 = acc[mt][nt][half * 2 + 0];
                const float v1 = acc[mt][nt][half * 2 + 1];
                if (MODE == 0) {
                    const float w0 = v0 + bias[c], w1 = v1 + bias[c + 1];
                    const int b = m >> 10, n = m & 1023;
                    const int ttt = c / DIM;
                    const int rr = c - ttt * DIM;
                    const int h = rr / HD, d = rr - h * HD;    // d even, d+1 same head
                    const int bh = b * NH + h;
                    if (ttt == 0)
                        *(__half2*)&g_q[((size_t)bh * NSEQ + n) * HD + d] =
                            __floats2half2_rn(w0 * SCALE, w1 * SCALE);
                    else if (ttt == 1)
                        *(__half2*)&g_k[((size_t)bh * NSEQ + n) * HD + d] =
                            __floats2half2_rn(w0, w1);
                    else {
                        g_v[((size_t)bh * HD + d) * NSEQ + n] = __float2half(w0);
                        g_v[((size_t)bh * HD + d + 1) * NSEQ + n] = __float2half(w1);
                    }
                } else {
                    float2 o = make_float2(v0 + bias[c], v1 + bias[c + 1]);
                    *(float2*)(C + (size_t)m * Nc + c) = o;
                }
            }
        }
    }
#undef MM_CP
}

// ---------------- K2: S = q @ k^T per (b,h), fp16 mma + ldmatrix --------------
__global__ __launch_bounds__(256) void qk_fp16() {
    __shared__ __half Qs[128][56];
    __shared__ __half Ks[128][56];

    const int tid = threadIdx.x;
    const int bh = blockIdx.z;
    const int q0 = blockIdx.y * 128;
    const int k0 = blockIdx.x * 128;

    const __half* Qg = g_q + (size_t)bh * NSEQ * HD;
    const __half* Kg = g_k + (size_t)bh * NSEQ * HD;

    const uint32_t sq = (uint32_t)__cvta_generic_to_shared(&Qs[0][0]);
    const uint32_t sk = (uint32_t)__cvta_generic_to_shared(&Ks[0][0]);

#pragma unroll
    for (int j = 0; j < 3; j++) {
        const int i = tid + 256 * j;
        const int r = i / 6, c = (i % 6) * 8;
        CP16(sq + (uint32_t)(r * 56 + c) * 2, Qg + (size_t)(q0 + r) * HD + c);
        CP16(sk + (uint32_t)(r * 56 + c) * 2, Kg + (size_t)(k0 + r) * HD + c);
    }
    CP_COMMIT();
    CP_WAIT(0);
    __syncthreads();

    const int warp = tid >> 5, lane = tid & 31;
    const int wm = warp >> 2, wn = warp & 3;
    const int g = lane >> 2, t = lane & 3;

    const uint32_t a_off = (uint32_t)((lane & 15) * 56 + (lane >> 4) * 8) * 2;
    const uint32_t b_off = (uint32_t)((((lane >> 4) << 3) + (lane & 7)) * 56 +
                                      (((lane >> 3) & 1) << 3)) * 2;

    float acc[4][4][4];
#pragma unroll
    for (int i = 0; i < 4; i++)
#pragma unroll
        for (int j = 0; j < 4; j++)
#pragma unroll
            for (int e = 0; e < 4; e++) acc[i][j][e] = 0.f;

#pragma unroll
    for (int ks = 0; ks < 3; ks++) {
        const uint32_t kb = (uint32_t)(ks * 16) * 2;
        uint32_t af[4][4], bf[4][2];
#pragma unroll
        for (int mt = 0; mt < 4; mt++)
            ldsm4(af[mt][0], af[mt][1], af[mt][2], af[mt][3],
                  sq + (uint32_t)((wm * 64 + mt * 16) * 56) * 2 + kb + a_off);
#pragma unroll
        for (int ntp = 0; ntp < 2; ntp++)
            ldsm4(bf[2 * ntp][0], bf[2 * ntp][1], bf[2 * ntp + 1][0], bf[2 * ntp + 1][1],
                  sk + (uint32_t)((wn * 32 + ntp * 16) * 56) * 2 + kb + b_off);
#pragma unroll
        for (int mt = 0; mt < 4; mt++)
#pragma unroll
            for (int nt = 0; nt < 4; nt++) mma16h(acc[mt][nt], af[mt], bf[nt]);
    }

    __half* Sg = g_S + (size_t)bh * NSEQ * NSEQ;
#pragma unroll
    for (int mt = 0; mt < 4; mt++)
#pragma unroll
        for (int nt = 0; nt < 4; nt++)
#pragma unroll
            for (int half = 0; half < 2; half++) {
                const int m = q0 + wm * 64 + mt * 16 + g + half * 8;
                const int c = k0 + wn * 32 + nt * 8 + 2 * t;
                *(__half2*)(Sg + (size_t)m * NSEQ + c) =
                    __floats2half2_rn(acc[mt][nt][half * 2], acc[mt][nt][half * 2 + 1]);
            }
}

// ---------------- K3: mix1 -> softmax -> mix2, all-fp16 smem ------------------
// One block per (b,q). s[16][SPH] fp16 (33KB static). Mixes: 1 ldmatrix.x2.trans
// + 1 fp16 mma per warp per 8-column group.
__global__ __launch_bounds__(256) void mix_softmax_kernel(
    const float* __restrict__ wl, const float* __restrict__ bl,
    const float* __restrict__ ww, const float* __restrict__ bw) {
    __shared__ __half s[NH][SPH];

    const int tid = threadIdx.x;
    const int lane = tid & 31, warp = tid >> 5;
    const int ar = lane >> 2;     // C/A row group (g)
    const int ac = lane & 3;      // C/A col-in-group (t)
    const int bq = blockIdx.x;
    const int b = bq >> 10, q = bq & 1023;

    const uint32_t ss = (uint32_t)__cvta_generic_to_shared(&s[0][0]);

    // fp16 A fragments for W_l / W_w  (A[m=g][k=h], row-major m16k16)
    uint32_t la[4], wa[4];
    la[0] = packh2(wl[ar * NH + 2 * ac], wl[ar * NH + 2 * ac + 1]);
    la[1] = packh2(wl[(ar + 8) * NH + 2 * ac], wl[(ar + 8) * NH + 2 * ac + 1]);
    la[2] = packh2(wl[ar * NH + 2 * ac + 8], wl[ar * NH + 2 * ac + 9]);
    la[3] = packh2(wl[(ar + 8) * NH + 2 * ac + 8], wl[(ar + 8) * NH + 2 * ac + 9]);
    wa[0] = packh2(ww[ar * NH + 2 * ac], ww[ar * NH + 2 * ac + 1]);
    wa[1] = packh2(ww[(ar + 8) * NH + 2 * ac], ww[(ar + 8) * NH + 2 * ac + 1]);
    wa[2] = packh2(ww[ar * NH + 2 * ac + 8], ww[ar * NH + 2 * ac + 9]);
    wa[3] = packh2(ww[(ar + 8) * NH + 2 * ac + 8], ww[(ar + 8) * NH + 2 * ac + 9]);
    const float bl0 = bl[ar], bl1 = bl[ar + 8];
    const float bw0 = bw[ar], bw1 = bw[ar + 8];

    const size_t rowbase = (size_t)(b * NH) * NSEQ * NSEQ + (size_t)q * NSEQ;

    // load all 16 head-rows via cp.async (16 x 2KB)
#pragma unroll
    for (int j = 0; j < 8; j++) {
        const int i = tid + 256 * j;
        const int h = i >> 7, c = (i & 127) * 8;
        CP16(ss + (uint32_t)(h * SPH + c) * 2,
             g_S + rowbase + (size_t)h * NSEQ * NSEQ + c);
    }
    CP_COMMIT();
    CP_WAIT(0);
    __syncthreads();

    const uint32_t bt_off = (uint32_t)((lane & 15) * SPH) * 2;  // trans-B row addr

    // ---- mix1 (in place; warp owns cols [warp*128, +128)) ----
#pragma unroll 4
    for (int c0 = warp * 128; c0 < warp * 128 + 128; c0 += 8) {
        uint32_t bf[2];
        ldsm2t(bf[0], bf[1], ss + bt_off + (uint32_t)c0 * 2);
        float c[4] = {bl0, bl0, bl1, bl1};
        mma16h(c, la, bf);
        *(__half2*)&s[ar][c0 + 2 * ac] = __floats2half2_rn(c[0], c[1]);
        *(__half2*)&s[ar + 8][c0 + 2 * ac] = __floats2half2_rn(c[2], c[3]);
    }
    __syncthreads();

    // ---- softmax per head row (fp32 math on fp16 data) ----
    for (int gg = warp; gg < NH; gg += 8) {
        __half2* row = (__half2*)&s[gg][0];     // 512 half2
        float mx = -1e30f;
        for (int k = lane; k < 512; k += 32) {
            float2 f = __half22float2(row[k]);
            mx = fmaxf(mx, fmaxf(f.x, f.y));
        }
#pragma unroll
        for (int off = 16; off > 0; off >>= 1) mx = fmaxf(mx, __shfl_xor_sync(0xffffffffu, mx, off));
        float sum = 0.f;
        for (int k = lane; k < 512; k += 32) {
            float2 f = __half22float2(row[k]);
            float e0 = __expf(f.x - mx), e1 = __expf(f.y - mx);
            row[k] = __floats2half2_rn(e0, e1);
            sum += e0 + e1;
        }
#pragma unroll
        for (int off = 16; off > 0; off >>= 1) sum += __shfl_xor_sync(0xffffffffu, sum, off);
        const float inv = 1.f / sum;
        for (int k = lane; k < 512; k += 32) {
            float2 f = __half22float2(row[k]);
            row[k] = __floats2half2_rn(f.x * inv, f.y * inv);
        }
    }
    __syncthreads();

    // ---- mix2, write fp16 to g_S ----
#pragma unroll 4
    for (int c0 = warp * 128; c0 < warp * 128 + 128; c0 += 8) {
        uint32_t bf[2];
        ldsm2t(bf[0], bf[1], ss + bt_off + (uint32_t)c0 * 2);
        float c[4] = {bw0, bw0, bw1, bw1};
        mma16h(c, wa, bf);
        *(__half2*)(g_S + rowbase + (size_t)ar * NSEQ * NSEQ + c0 + 2 * ac) =
            __floats2half2_rn(c[0], c[1]);
        *(__half2*)(g_S + rowbase + (size_t)(ar + 8) * NSEQ * NSEQ + c0 + 2 * ac) =
            __floats2half2_rn(c[2], c[3]);
    }
}

// ---------------- K4: O = P @ V per (b,h), fp16 mma + ldmatrix + cp.async -----
__global__ __launch_bounds__(256) void pv_fp16() {
    __shared__ __half Ps[2][128][40];
    __shared__ __half Vs[2][HD][40];

    const int bh = blockIdx.z;
    const int tid = threadIdx.x;
    const int qbase = blockIdx.x * 128;
    const __half* Pg = g_S + (size_t)bh * NSEQ * NSEQ + (size_t)qbase * NSEQ;
    const __half* Vg = g_v + (size_t)bh * HD * NSEQ;   // [d][n]

    const int warp = tid >> 5, lane = tid & 31;
    const int wm = warp >> 1, wn = warp & 1;
    const int g = lane >> 2, t = lane & 3;

    const uint32_t psa = (uint32_t)__cvta_generic_to_shared(&Ps[0][0][0]);
    const uint32_t vsa = (uint32_t)__cvta_generic_to_shared(&Vs[0][0][0]);
    const uint32_t PSZ = 128 * 40 * 2;
    const uint32_t VSZ = HD * 40 * 2;

    const uint32_t a_off = (uint32_t)((lane & 15) * 40 + (lane >> 4) * 8) * 2;
    const uint32_t b_off = (uint32_t)((((lane >> 4) << 3) + (lane & 7)) * 40 +
                                      (((lane >> 3) & 1) << 3)) * 2;
    const uint32_t b2_off = (uint32_t)((lane & 7) * 40 + (((lane >> 3) & 1) << 3)) * 2;

#define PV_CP(buf, kt)                                                          \
    do {                                                                        \
        _Pragma("unroll")                                                       \
        for (int j = 0; j < 2; j++) {                                           \
            const int i = tid + 256 * j;                                        \
            const int r = i >> 2, c = (i & 3) * 8;                              \
            CP16(psa + (buf) * PSZ + (uint32_t)(r * 40 + c) * 2,                \
                 Pg + (size_t)r * NSEQ + (kt) + c);                             \
        }                                                                       \
        if (tid < 192) {                                                        \
            const int d = tid >> 2, c = (tid & 3) * 8;                          \
            CP16(vsa + (buf) * VSZ + (uint32_t)(d * 40 + c) * 2,                \
                 Vg + (size_t)d * NSEQ + (kt) + c);                             \
        }                                                                       \
        CP_COMMIT();                                                            \
    } while (0)

    float acc[2][3][4];
#pragma unroll
    for (int i = 0; i < 2; i++)
#pragma unroll
        for (int j = 0; j < 3; j++)
#pragma unroll
            for (int e = 0; e < 4; e++) acc[i][j][e] = 0.f;

    PV_CP(0, 0);
    CP_WAIT(0);
    __syncthreads();

    int buf = 0;
    for (int kt = 32;; kt += 32) {
        const bool more = kt < NSEQ;
        if (more) PV_CP(buf ^ 1, kt);
#pragma unroll
        for (int ks = 0; ks < 2; ks++) {
            const uint32_t kb = (uint32_t)(ks * 16) * 2;
            uint32_t af[2][4], bf[3][2];
#pragma unroll
            for (int mt = 0; mt < 2; mt++)
                ldsm4(af[mt][0], af[mt][1], af[mt][2], af[mt][3],
                      psa + buf * PSZ + (uint32_t)((wm * 32 + mt * 16) * 40) * 2 + kb + a_off);
            ldsm4(bf[0][0], bf[0][1], bf[1][0], bf[1][1],
                  vsa + buf * VSZ + (uint32_t)((wn * 24) * 40) * 2 + kb + b_off);
            ldsm2(bf[2][0], bf[2][1],
                  vsa + buf * VSZ + (uint32_t)((wn * 24 + 16) * 40) * 2 + kb + b2_off);
#pragma unroll
            for (int mt = 0; mt < 2; mt++)
#pragma unroll
                for (int nt = 0; nt < 3; nt++) mma16h(acc[mt][nt], af[mt], bf[nt]);
        }
        if (!more) break;
        CP_WAIT(0);
        __syncthreads();
        buf ^= 1;
    }

    const int b = bh >> 4, h = bh & 15;
#pragma unroll
    for (int mt = 0; mt < 2; mt++)
#pragma unroll
        for (int nt = 0; nt < 3; nt++)
#pragma unroll
            for (int half = 0; half < 2; half++) {
                const int q = qbase + wm * 32 + mt * 16 + g + half * 8;
                const int d = wn * 24 + nt * 8 + 2 * t;
                *(__half2*)(g_O + (size_t)(b * NSEQ + q) * DIM + h * HD + d) =
                    __floats2half2_rn(acc[mt][nt][half * 2], acc[mt][nt][half * 2 + 1]);
            }
#undef PV_CP
}

// ---------------- launch ------------------------------------------------------
extern "C" void kernel_launch(void* const* d_in, const int* in_sizes, int n_in,
                              void* d_out, int out_size) {
    const float* x      = (const float*)d_in[0];
    const float* w_qkv  = (const float*)d_in[1];
    const float* b_qkv  = (const float*)d_in[2];
    const float* w_l    = (const float*)d_in[3];
    const float* b_l    = (const float*)d_in[4];
    const float* w_w    = (const float*)d_in[5];
    const float* b_w    = (const float*)d_in[6];
    const float* w_proj = (const float*)d_in[7];
    const float* b_proj = (const float*)d_in[8];
    float* out = (float*)d_out;

    const int mm_smem = 2 * 3 * 128 * 40 * 2;   // 61440 B (3-stage, A+W)
    cudaFuncSetAttribute(mm_fp16<0>, cudaFuncAttributeMaxDynamicSharedMemorySize, mm_smem);
    cudaFuncSetAttribute(mm_fp16<1>, cudaFuncAttributeMaxDynamicSharedMemorySize, mm_smem);

    __half* xh;  cudaGetSymbolAddress((void**)&xh, g_xh);
    __half* wqh; cudaGetSymbolAddress((void**)&wqh, g_wqkvh);
    __half* wph; cudaGetSymbolAddress((void**)&wph, g_wprojh);
    __half* Oh;  cudaGetSymbolAddress((void**)&Oh, g_O);

    // K0: fp32 -> fp16 conversions
    f2h_kernel<<<592, 256>>>(x, xh, BATCH * NSEQ * DIM / 4);
    f2h_kernel<<<296, 256>>>(w_qkv, wqh, 3 * DIM * DIM / 4);
    f2h_kernel<<<148, 256>>>(w_proj, wph, DIM * DIM / 4);

    // K1: QKV projection  [M=8192, N=2304, K=768]
    mm_fp16<0><<<dim3(3 * DIM / 128, BATCH * NSEQ / 128), 256, mm_smem>>>(
        xh, wqh, b_qkv, nullptr, DIM, 3 * DIM);
    // K2: logits S = q @ k^T per (b,h)
    qk_fp16<<<dim3(NSEQ / 128, NSEQ / 128, BATCH * NH), 256>>>();
    // K3: mix1 + softmax + mix2 (in place, all-fp16)
    mix_softmax_kernel<<<BATCH * NSEQ, 256>>>(w_l, b_l, w_w, b_w);
    // K4: P @ V -> g_O (fp16)
    pv_fp16<<<dim3(NSEQ / 128, 1, BATCH * NH), 256>>>();
    // K5: output projection  [M=8192, N=768, K=768]
    mm_fp16<1><<<dim3(DIM / 128, BATCH * NSEQ / 128), 256, mm_smem>>>(
        Oh, wph, b_proj, out, DIM, DIM);
}

// round 12
// speedup vs baseline: 16.2571x; 1.0435x over previous
#include <cuda_runtime.h>
#include <cuda_fp16.h>
#include <cstdint>

#define BATCH 8
#define NSEQ 1024
#define DIM 768
#define NH 16
#define HD 48
#define SCALE 0.14433756729740643f  /* 48^-0.5 */
#define SPH 1032                     /* fp16 smem stride (halfs) for mix kernel */

// ---------------- scratch (static __device__, allocation-guard safe) ----------
__device__ __align__(256) __half g_xh[BATCH * NSEQ * DIM];
__device__ __align__(256) __half g_wqkvh[3 * DIM * DIM];
__device__ __align__(256) __half g_wprojh[DIM * DIM];
__device__ __align__(256) __half g_q[BATCH * NH * NSEQ * HD];       // [b][h][n][d] (pre-scaled)
__device__ __align__(256) __half g_k[BATCH * NH * NSEQ * HD];       // [b][h][n][d]
__device__ __align__(256) __half g_v[BATCH * NH * HD * NSEQ];       // [b][h][d][n]  TRANSPOSED
__device__ __align__(256) __half g_S[(size_t)BATCH * NH * NSEQ * NSEQ];
__device__ __align__(256) __half g_O[BATCH * NSEQ * DIM];           // attn out pre-proj (fp16)

// ---------------- helpers -----------------------------------------------------
__device__ __forceinline__ void mma16h(float* c, const uint32_t* a, const uint32_t* b) {
    asm volatile(
        "mma.sync.aligned.m16n8k16.row.col.f32.f16.f16.f32 "
        "{%0,%1,%2,%3},{%4,%5,%6,%7},{%8,%9},{%0,%1,%2,%3};"
        : "+f"(c[0]), "+f"(c[1]), "+f"(c[2]), "+f"(c[3])
        : "r"(a[0]), "r"(a[1]), "r"(a[2]), "r"(a[3]), "r"(b[0]), "r"(b[1]));
}
__device__ __forceinline__ void ldsm4(uint32_t& r0, uint32_t& r1, uint32_t& r2, uint32_t& r3,
                                      uint32_t addr) {
    asm volatile("ldmatrix.sync.aligned.m8n8.x4.shared.b16 {%0,%1,%2,%3}, [%4];"
        : "=r"(r0), "=r"(r1), "=r"(r2), "=r"(r3) : "r"(addr));
}
__device__ __forceinline__ void ldsm2(uint32_t& r0, uint32_t& r1, uint32_t addr) {
    asm volatile("ldmatrix.sync.aligned.m8n8.x2.shared.b16 {%0,%1}, [%2];"
        : "=r"(r0), "=r"(r1) : "r"(addr));
}
__device__ __forceinline__ void ldsm2t(uint32_t& r0, uint32_t& r1, uint32_t addr) {
    asm volatile("ldmatrix.sync.aligned.m8n8.x2.trans.shared.b16 {%0,%1}, [%2];"
        : "=r"(r0), "=r"(r1) : "r"(addr));
}
__device__ __forceinline__ uint32_t packh2(float x, float y) {
    __half2 h = __floats2half2_rn(x, y);
    return *(uint32_t*)&h;
}

#define CP16(dst_u32, src_ptr) \
    asm volatile("cp.async.cg.shared.global [%0], [%1], 16;" :: "r"(dst_u32), "l"(src_ptr))
#define CP_COMMIT()  asm volatile("cp.async.commit_group;" ::)
#define CP_WAIT(n)   asm volatile("cp.async.wait_group %0;" :: "n"(n))

// ---------------- K0: fp32 -> fp16 conversion ---------------------------------
__global__ __launch_bounds__(256) void f2h_kernel(
    const float* __restrict__ in, __half* __restrict__ out, int n4) {
    for (int i = blockIdx.x * 256 + threadIdx.x; i < n4; i += gridDim.x * 256) {
        float4 v = ((const float4*)in)[i];
        ((__half2*)out)[2 * i]     = __floats2half2_rn(v.x, v.y);
        ((__half2*)out)[2 * i + 1] = __floats2half2_rn(v.z, v.w);
    }
}

// ---------------- mm_fp16: qkv (MODE 0) & proj (MODE 1) -----------------------
// 512 threads, block tile 256(M) x 128(N), K-tile 32, 2-stage cp.async.
// 16 warps (4M x 4N), warp tile 64x32.
#define ABUF (256 * 40 * 2)
#define WBUF (128 * 40 * 2)
template <int MODE>
__global__ __launch_bounds__(512) void mm_fp16(
    const __half* __restrict__ A, const __half* __restrict__ W,
    const float* __restrict__ bias, float* __restrict__ C, int K, int Nc) {
    extern __shared__ __half smem_mm[];

    const int tid = threadIdx.x;
    const int m0 = blockIdx.y * 256;
    const int n0 = blockIdx.x * 128;

    const int warp = tid >> 5, lane = tid & 31;
    const int wm = warp >> 2, wn = warp & 3;   // 4 x 4 warps
    const int g = lane >> 2, t = lane & 3;

    const uint32_t sa = (uint32_t)__cvta_generic_to_shared(smem_mm);
    const uint32_t sw = sa + 2 * ABUF;

    const uint32_t a_off = (uint32_t)((lane & 15) * 40 + (lane >> 4) * 8) * 2;
    const uint32_t b_off = (uint32_t)((((lane >> 4) << 3) + (lane & 7)) * 40 +
                                      (((lane >> 3) & 1) << 3)) * 2;

#define MM_CP(buf, kt)                                                         \
    do {                                                                       \
        _Pragma("unroll")                                                      \
        for (int j = 0; j < 2; j++) {         /* A: 256 rows x 4 chunks */     \
            const int i = tid + 512 * j;                                       \
            const int r = i >> 2, c = (i & 3) * 8;                             \
            CP16(sa + (buf) * ABUF + (uint32_t)(r * 40 + c) * 2,               \
                 A + (size_t)(m0 + r) * K + (kt) + c);                         \
        }                                                                      \
        {                                      /* W: 128 rows x 4 chunks */    \
            const int r = tid >> 2, c = (tid & 3) * 8;                         \
            if (tid < 512) {}                                                  \
            CP16(sw + (buf) * WBUF + (uint32_t)(r * 40 + c) * 2,               \
                 W + (size_t)(n0 + r) * K + (kt) + c);                         \
        }                                                                      \
        CP_COMMIT();                                                           \
    } while (0)

    float acc[4][4][4];
#pragma unroll
    for (int i = 0; i < 4; i++)
#pragma unroll
        for (int j = 0; j < 4; j++)
#pragma unroll
            for (int e = 0; e < 4; e++) acc[i][j][e] = 0.f;

    MM_CP(0, 0);
    CP_WAIT(0);
    __syncthreads();

    int buf = 0;
    for (int kt = 32;; kt += 32) {
        const bool more = kt < K;
        if (more) MM_CP(buf ^ 1, kt);
#pragma unroll
        for (int ks = 0; ks < 2; ks++) {
            const uint32_t kb = (uint32_t)(ks * 16) * 2;
            uint32_t af[4][4], bf[4][2];
#pragma unroll
            for (int mt = 0; mt < 4; mt++)
                ldsm4(af[mt][0], af[mt][1], af[mt][2], af[mt][3],
                      sa + buf * ABUF + (uint32_t)((wm * 64 + mt * 16) * 40) * 2 + kb + a_off);
#pragma unroll
            for (int ntp = 0; ntp < 2; ntp++)
                ldsm4(bf[2 * ntp][0], bf[2 * ntp][1], bf[2 * ntp + 1][0], bf[2 * ntp + 1][1],
                      sw + buf * WBUF + (uint32_t)((wn * 32 + ntp * 16) * 40) * 2 + kb + b_off);
#pragma unroll
            for (int mt = 0; mt < 4; mt++)
#pragma unroll
                for (int nt = 0; nt < 4; nt++) mma16h(acc[mt][nt], af[mt], bf[nt]);
        }
        if (!more) break;
        CP_WAIT(0);
        __syncthreads();
        buf ^= 1;
    }

#pragma unroll
    for (int mt = 0; mt < 4; mt++) {
#pragma unroll
        for (int nt = 0; nt < 4; nt++) {
#pragma unroll
            for (int half = 0; half < 2; half++) {
                const int m = m0 + wm * 64 + mt * 16 + g + half * 8;
                const int c = n0 + wn * 32 + nt * 8 + 2 * t;   // always even
                const float v0 = acc[mt][nt][half * 2 + 0];
                const float v1 = acc[mt][nt][half * 2 + 1];
                if (MODE == 0) {
                    const float w0 = v0 + bias[c], w1 = v1 + bias[c + 1];
                    const int b = m >> 10, n = m & 1023;
                    const int ttt = c / DIM;
                    const int rr = c - ttt * DIM;
                    const int h = rr / HD, d = rr - h * HD;    // d even, d+1 same head
                    const int bh = b * NH + h;
                    if (ttt == 0)
                        *(__half2*)&g_q[((size_t)bh * NSEQ + n) * HD + d] =
                            __floats2half2_rn(w0 * SCALE, w1 * SCALE);
                    else if (ttt == 1)
                        *(__half2*)&g_k[((size_t)bh * NSEQ + n) * HD + d] =
                            __floats2half2_rn(w0, w1);
                    else {
                        g_v[((size_t)bh * HD + d) * NSEQ + n] = __float2half(w0);
                        g_v[((size_t)bh * HD + d + 1) * NSEQ + n] = __float2half(w1);
                    }
                } else {
                    float2 o = make_float2(v0 + bias[c], v1 + bias[c + 1]);
                    *(float2*)(C + (size_t)m * Nc + c) = o;
                }
            }
        }
    }
#undef MM_CP
}

// ---------------- K2: S = q @ k^T per (b,h), fp16 mma + ldmatrix --------------
__global__ __launch_bounds__(256) void qk_fp16() {
    __shared__ __half Qs[128][56];
    __shared__ __half Ks[128][56];

    const int tid = threadIdx.x;
    const int bh = blockIdx.z;
    const int q0 = blockIdx.y * 128;
    const int k0 = blockIdx.x * 128;

    const __half* Qg = g_q + (size_t)bh * NSEQ * HD;
    const __half* Kg = g_k + (size_t)bh * NSEQ * HD;

    const uint32_t sq = (uint32_t)__cvta_generic_to_shared(&Qs[0][0]);
    const uint32_t sk = (uint32_t)__cvta_generic_to_shared(&Ks[0][0]);

#pragma unroll
    for (int j = 0; j < 3; j++) {
        const int i = tid + 256 * j;
        const int r = i / 6, c = (i % 6) * 8;
        CP16(sq + (uint32_t)(r * 56 + c) * 2, Qg + (size_t)(q0 + r) * HD + c);
        CP16(sk + (uint32_t)(r * 56 + c) * 2, Kg + (size_t)(k0 + r) * HD + c);
    }
    CP_COMMIT();
    CP_WAIT(0);
    __syncthreads();

    const int warp = tid >> 5, lane = tid & 31;
    const int wm = warp >> 2, wn = warp & 3;
    const int g = lane >> 2, t = lane & 3;

    const uint32_t a_off = (uint32_t)((lane & 15) * 56 + (lane >> 4) * 8) * 2;
    const uint32_t b_off = (uint32_t)((((lane >> 4) << 3) + (lane & 7)) * 56 +
                                      (((lane >> 3) & 1) << 3)) * 2;

    float acc[4][4][4];
#pragma unroll
    for (int i = 0; i < 4; i++)
#pragma unroll
        for (int j = 0; j < 4; j++)
#pragma unroll
            for (int e = 0; e < 4; e++) acc[i][j][e] = 0.f;

#pragma unroll
    for (int ks = 0; ks < 3; ks++) {
        const uint32_t kb = (uint32_t)(ks * 16) * 2;
        uint32_t af[4][4], bf[4][2];
#pragma unroll
        for (int mt = 0; mt < 4; mt++)
            ldsm4(af[mt][0], af[mt][1], af[mt][2], af[mt][3],
                  sq + (uint32_t)((wm * 64 + mt * 16) * 56) * 2 + kb + a_off);
#pragma unroll
        for (int ntp = 0; ntp < 2; ntp++)
            ldsm4(bf[2 * ntp][0], bf[2 * ntp][1], bf[2 * ntp + 1][0], bf[2 * ntp + 1][1],
                  sk + (uint32_t)((wn * 32 + ntp * 16) * 56) * 2 + kb + b_off);
#pragma unroll
        for (int mt = 0; mt < 4; mt++)
#pragma unroll
            for (int nt = 0; nt < 4; nt++) mma16h(acc[mt][nt], af[mt], bf[nt]);
    }

    __half* Sg = g_S + (size_t)bh * NSEQ * NSEQ;
#pragma unroll
    for (int mt = 0; mt < 4; mt++)
#pragma unroll
        for (int nt = 0; nt < 4; nt++)
#pragma unroll
            for (int half = 0; half < 2; half++) {
                const int m = q0 + wm * 64 + mt * 16 + g + half * 8;
                const int c = k0 + wn * 32 + nt * 8 + 2 * t;
                *(__half2*)(Sg + (size_t)m * NSEQ + c) =
                    __floats2half2_rn(acc[mt][nt][half * 2], acc[mt][nt][half * 2 + 1]);
            }
}

// ---------------- K3: mix1 -> softmax -> mix2, all-fp16 smem ------------------
// mix2 results staged in smem, then one coalesced float4 copy to g_S.
__global__ __launch_bounds__(256) void mix_softmax_kernel(
    const float* __restrict__ wl, const float* __restrict__ bl,
    const float* __restrict__ ww, const float* __restrict__ bw) {
    __shared__ __half s[NH][SPH];

    const int tid = threadIdx.x;
    const int lane = tid & 31, warp = tid >> 5;
    const int ar = lane >> 2;
    const int ac = lane & 3;
    const int bq = blockIdx.x;
    const int b = bq >> 10, q = bq & 1023;

    const uint32_t ss = (uint32_t)__cvta_generic_to_shared(&s[0][0]);

    uint32_t la[4], wa[4];
    la[0] = packh2(wl[ar * NH + 2 * ac], wl[ar * NH + 2 * ac + 1]);
    la[1] = packh2(wl[(ar + 8) * NH + 2 * ac], wl[(ar + 8) * NH + 2 * ac + 1]);
    la[2] = packh2(wl[ar * NH + 2 * ac + 8], wl[ar * NH + 2 * ac + 9]);
    la[3] = packh2(wl[(ar + 8) * NH + 2 * ac + 8], wl[(ar + 8) * NH + 2 * ac + 9]);
    wa[0] = packh2(ww[ar * NH + 2 * ac], ww[ar * NH + 2 * ac + 1]);
    wa[1] = packh2(ww[(ar + 8) * NH + 2 * ac], ww[(ar + 8) * NH + 2 * ac + 1]);
    wa[2] = packh2(ww[ar * NH + 2 * ac + 8], ww[ar * NH + 2 * ac + 9]);
    wa[3] = packh2(ww[(ar + 8) * NH + 2 * ac + 8], ww[(ar + 8) * NH + 2 * ac + 9]);
    const float bl0 = bl[ar], bl1 = bl[ar + 8];
    const float bw0 = bw[ar], bw1 = bw[ar + 8];

    const size_t rowbase = (size_t)(b * NH) * NSEQ * NSEQ + (size_t)q * NSEQ;

#pragma unroll
    for (int j = 0; j < 8; j++) {
        const int i = tid + 256 * j;
        const int h = i >> 7, c = (i & 127) * 8;
        CP16(ss + (uint32_t)(h * SPH + c) * 2,
             g_S + rowbase + (size_t)h * NSEQ * NSEQ + c);
    }
    CP_COMMIT();
    CP_WAIT(0);
    __syncthreads();

    const uint32_t bt_off = (uint32_t)((lane & 15) * SPH) * 2;

    // mix1 (in place; warp owns cols [warp*128, +128))
#pragma unroll 4
    for (int c0 = warp * 128; c0 < warp * 128 + 128; c0 += 8) {
        uint32_t bf[2];
        ldsm2t(bf[0], bf[1], ss + bt_off + (uint32_t)c0 * 2);
        float c[4] = {bl0, bl0, bl1, bl1};
        mma16h(c, la, bf);
        *(__half2*)&s[ar][c0 + 2 * ac] = __floats2half2_rn(c[0], c[1]);
        *(__half2*)&s[ar + 8][c0 + 2 * ac] = __floats2half2_rn(c[2], c[3]);
    }
    __syncthreads();

    // softmax per head row
    for (int gg = warp; gg < NH; gg += 8) {
        __half2* row = (__half2*)&s[gg][0];
        float mx = -1e30f;
        for (int k = lane; k < 512; k += 32) {
            float2 f = __half22float2(row[k]);
            mx = fmaxf(mx, fmaxf(f.x, f.y));
        }
#pragma unroll
        for (int off = 16; off > 0; off >>= 1) mx = fmaxf(mx, __shfl_xor_sync(0xffffffffu, mx, off));
        float sum = 0.f;
        for (int k = lane; k < 512; k += 32) {
            float2 f = __half22float2(row[k]);
            float e0 = __expf(f.x - mx), e1 = __expf(f.y - mx);
            row[k] = __floats2half2_rn(e0, e1);
            sum += e0 + e1;
        }
#pragma unroll
        for (int off = 16; off > 0; off >>= 1) sum += __shfl_xor_sync(0xffffffffu, sum, off);
        const float inv = 1.f / sum;
        for (int k = lane; k < 512; k += 32) {
            float2 f = __half22float2(row[k]);
            row[k] = __floats2half2_rn(f.x * inv, f.y * inv);
        }
    }
    __syncthreads();

    // mix2 in place (same stripe discipline as mix1)
#pragma unroll 4
    for (int c0 = warp * 128; c0 < warp * 128 + 128; c0 += 8) {
        uint32_t bf[2];
        ldsm2t(bf[0], bf[1], ss + bt_off + (uint32_t)c0 * 2);
        float c[4] = {bw0, bw0, bw1, bw1};
        mma16h(c, wa, bf);
        *(__half2*)&s[ar][c0 + 2 * ac] = __floats2half2_rn(c[0], c[1]);
        *(__half2*)&s[ar + 8][c0 + 2 * ac] = __floats2half2_rn(c[2], c[3]);
    }
    __syncthreads();

    // coalesced store s -> g_S (float4 = 8 halfs per thread-iteration)
#pragma unroll
    for (int j = 0; j < 8; j++) {
        const int i = tid + 256 * j;
        const int h = i >> 7, c = (i & 127) * 8;
        float4 v = *(const float4*)&s[h][c];
        *(float4*)(g_S + rowbase + (size_t)h * NSEQ * NSEQ + c) = v;
    }
}

// ---------------- K4: O = P @ V per (b,h), fp16 mma + ldmatrix + cp.async -----
__global__ __launch_bounds__(256) void pv_fp16() {
    __shared__ __half Ps[2][128][40];
    __shared__ __half Vs[2][HD][40];

    const int bh = blockIdx.z;
    const int tid = threadIdx.x;
    const int qbase = blockIdx.x * 128;
    const __half* Pg = g_S + (size_t)bh * NSEQ * NSEQ + (size_t)qbase * NSEQ;
    const __half* Vg = g_v + (size_t)bh * HD * NSEQ;   // [d][n]

    const int warp = tid >> 5, lane = tid & 31;
    const int wm = warp >> 1, wn = warp & 1;
    const int g = lane >> 2, t = lane & 3;

    const uint32_t psa = (uint32_t)__cvta_generic_to_shared(&Ps[0][0][0]);
    const uint32_t vsa = (uint32_t)__cvta_generic_to_shared(&Vs[0][0][0]);
    const uint32_t PSZ = 128 * 40 * 2;
    const uint32_t VSZ = HD * 40 * 2;

    const uint32_t a_off = (uint32_t)((lane & 15) * 40 + (lane >> 4) * 8) * 2;
    const uint32_t b_off = (uint32_t)((((lane >> 4) << 3) + (lane & 7)) * 40 +
                                      (((lane >> 3) & 1) << 3)) * 2;
    const uint32_t b2_off = (uint32_t)((lane & 7) * 40 + (((lane >> 3) & 1) << 3)) * 2;

#define PV_CP(buf, kt)                                                          \
    do {                                                                        \
        _Pragma("unroll")                                                       \
        for (int j = 0; j < 2; j++) {                                           \
            const int i = tid + 256 * j;                                        \
            const int r = i >> 2, c = (i & 3) * 8;                              \
            CP16(psa + (buf) * PSZ + (uint32_t)(r * 40 + c) * 2,                \
                 Pg + (size_t)r * NSEQ + (kt) + c);                             \
        }                                                                       \
        if (tid < 192) {                                                        \
            const int d = tid >> 2, c = (tid & 3) * 8;                          \
            CP16(vsa + (buf) * VSZ + (uint32_t)(d * 40 + c) * 2,                \
                 Vg + (size_t)d * NSEQ + (kt) + c);                             \
        }                                                                       \
        CP_COMMIT();                                                            \
    } while (0)

    float acc[2][3][4];
#pragma unroll
    for (int i = 0; i < 2; i++)
#pragma unroll
        for (int j = 0; j < 3; j++)
#pragma unroll
            for (int e = 0; e < 4; e++) acc[i][j][e] = 0.f;

    PV_CP(0, 0);
    CP_WAIT(0);
    __syncthreads();

    int buf = 0;
    for (int kt = 32;; kt += 32) {
        const bool more = kt < NSEQ;
        if (more) PV_CP(buf ^ 1, kt);
#pragma unroll
        for (int ks = 0; ks < 2; ks++) {
            const uint32_t kb = (uint32_t)(ks * 16) * 2;
            uint32_t af[2][4], bf[3][2];
#pragma unroll
            for (int mt = 0; mt < 2; mt++)
                ldsm4(af[mt][0], af[mt][1], af[mt][2], af[mt][3],
                      psa + buf * PSZ + (uint32_t)((wm * 32 + mt * 16) * 40) * 2 + kb + a_off);
            ldsm4(bf[0][0], bf[0][1], bf[1][0], bf[1][1],
                  vsa + buf * VSZ + (uint32_t)((wn * 24) * 40) * 2 + kb + b_off);
            ldsm2(bf[2][0], bf[2][1],
                  vsa + buf * VSZ + (uint32_t)((wn * 24 + 16) * 40) * 2 + kb + b2_off);
#pragma unroll
            for (int mt = 0; mt < 2; mt++)
#pragma unroll
                for (int nt = 0; nt < 3; nt++) mma16h(acc[mt][nt], af[mt], bf[nt]);
        }
        if (!more) break;
        CP_WAIT(0);
        __syncthreads();
        buf ^= 1;
    }

    const int b = bh >> 4, h = bh & 15;
#pragma unroll
    for (int mt = 0; mt < 2; mt++)
#pragma unroll
        for (int nt = 0; nt < 3; nt++)
#pragma unroll
            for (int half = 0; half < 2; half++) {
                const int q = qbase + wm * 32 + mt * 16 + g + half * 8;
                const int d = wn * 24 + nt * 8 + 2 * t;
                *(__half2*)(g_O + (size_t)(b * NSEQ + q) * DIM + h * HD + d) =
                    __floats2half2_rn(acc[mt][nt][half * 2], acc[mt][nt][half * 2 + 1]);
            }
#undef PV_CP
}

// ---------------- launch ------------------------------------------------------
extern "C" void kernel_launch(void* const* d_in, const int* in_sizes, int n_in,
                              void* d_out, int out_size) {
    const float* x      = (const float*)d_in[0];
    const float* w_qkv  = (const float*)d_in[1];
    const float* b_qkv  = (const float*)d_in[2];
    const float* w_l    = (const float*)d_in[3];
    const float* b_l    = (const float*)d_in[4];
    const float* w_w    = (const float*)d_in[5];
    const float* b_w    = (const float*)d_in[6];
    const float* w_proj = (const float*)d_in[7];
    const float* b_proj = (const float*)d_in[8];
    float* out = (float*)d_out;

    const int mm_smem = 2 * ABUF + 2 * WBUF;   // 61440 B
    cudaFuncSetAttribute(mm_fp16<0>, cudaFuncAttributeMaxDynamicSharedMemorySize, mm_smem);
    cudaFuncSetAttribute(mm_fp16<1>, cudaFuncAttributeMaxDynamicSharedMemorySize, mm_smem);

    __half* xh;  cudaGetSymbolAddress((void**)&xh, g_xh);
    __half* wqh; cudaGetSymbolAddress((void**)&wqh, g_wqkvh);
    __half* wph; cudaGetSymbolAddress((void**)&wph, g_wprojh);
    __half* Oh;  cudaGetSymbolAddress((void**)&Oh, g_O);

    // K0: fp32 -> fp16 conversions
    f2h_kernel<<<592, 256>>>(x, xh, BATCH * NSEQ * DIM / 4);
    f2h_kernel<<<296, 256>>>(w_qkv, wqh, 3 * DIM * DIM / 4);
    f2h_kernel<<<148, 256>>>(w_proj, wph, DIM * DIM / 4);

    // K1: QKV projection  [M=8192, N=2304, K=768]
    mm_fp16<0><<<dim3(3 * DIM / 128, BATCH * NSEQ / 256), 512, mm_smem>>>(
        xh, wqh, b_qkv, nullptr, DIM, 3 * DIM);
    // K2: logits S = q @ k^T per (b,h)
    qk_fp16<<<dim3(NSEQ / 128, NSEQ / 128, BATCH * NH), 256>>>();
    // K3: mix1 + softmax + mix2 (in place, all-fp16, staged stores)
    mix_softmax_kernel<<<BATCH * NSEQ, 256>>>(w_l, b_l, w_w, b_w);
    // K4: P @ V -> g_O (fp16)
    pv_fp16<<<dim3(NSEQ / 128, 1, BATCH * NH), 256>>>();
    // K5: output projection  [M=8192, N=768, K=768]
    mm_fp16<1><<<dim3(DIM / 128, BATCH * NSEQ / 256), 512, mm_smem>>>(
        Oh, wph, b_proj, out, DIM, DIM);
}